// round 13
// baseline (speedup 1.0000x reference)
#include <cuda_runtime.h>
#include <cuda_bf16.h>
#include <stdint.h>
#include <math.h>

#define D_MODEL 768
#define HEADS   12
#define DH      64
#define SEQ     1024
#define BATCH   8
#define ROWS    (BATCH*SEQ)        /* 8192 */
#define ELEMS   (ROWS*D_MODEL)     /* 6291456 */
#define WEL     (D_MODEL*D_MODEL)  /* 589824 */

__device__ __nv_bfloat16 g_bf16[16ull * ELEMS + 16ull * WEL];

// ---------------------------------------------------------------------------
// PTX helpers
// ---------------------------------------------------------------------------
__device__ __forceinline__ uint32_t smem_u32(const void* p) {
    return (uint32_t)__cvta_generic_to_shared(p);
}
__device__ __forceinline__ void ldsm_x4(uint32_t r[4], uint32_t addr) {
    asm volatile("ldmatrix.sync.aligned.m8n8.x4.shared.b16 {%0,%1,%2,%3}, [%4];"
                 : "=r"(r[0]), "=r"(r[1]), "=r"(r[2]), "=r"(r[3]) : "r"(addr));
}
__device__ __forceinline__ void ldsm_x4_t(uint32_t r[4], uint32_t addr) {
    asm volatile("ldmatrix.sync.aligned.m8n8.x4.trans.shared.b16 {%0,%1,%2,%3}, [%4];"
                 : "=r"(r[0]), "=r"(r[1]), "=r"(r[2]), "=r"(r[3]) : "r"(addr));
}
__device__ __forceinline__ void mma_bf16(float d[4], const uint32_t a[4],
                                         const uint32_t b[2]) {
    asm volatile(
        "mma.sync.aligned.m16n8k16.row.col.f32.bf16.bf16.f32 "
        "{%0,%1,%2,%3}, {%4,%5,%6,%7}, {%8,%9}, {%0,%1,%2,%3};"
        : "+f"(d[0]), "+f"(d[1]), "+f"(d[2]), "+f"(d[3])
        : "r"(a[0]), "r"(a[1]), "r"(a[2]), "r"(a[3]), "r"(b[0]), "r"(b[1]));
}
__device__ __forceinline__ uint32_t pack_bf2(float a, float b) {
    __nv_bfloat162 t = __floats2bfloat162_rn(a, b);
    return *(uint32_t*)&t;
}
__device__ __forceinline__ void cp16(uint32_t s, const void* g) {
    asm volatile("cp.async.cg.shared.global [%0], [%1], 16;" :: "r"(s), "l"(g));
}
__device__ __forceinline__ void cp_commit() {
    asm volatile("cp.async.commit_group;" ::: "memory");
}
template<int N> __device__ __forceinline__ void cp_wait() {
    asm volatile("cp.async.wait_group %0;" :: "n"(N) : "memory");
}

// ---------------------------------------------------------------------------
// LayerNorm fused with hi/lo bf16 split. One block per row, 256 threads.
// ---------------------------------------------------------------------------
__global__ __launch_bounds__(256)
void ln_split_kernel(const float* __restrict__ x, const float* __restrict__ g,
                     const float* __restrict__ b,
                     __nv_bfloat16* __restrict__ ohi, __nv_bfloat16* __restrict__ olo)
{
    __shared__ float red[16];
    int row = blockIdx.x;
    int tid = threadIdx.x;
    const float* xp = x + (size_t)row * D_MODEL;
    float v0 = xp[tid], v1 = xp[tid + 256], v2 = xp[tid + 512];
    float s  = v0 + v1 + v2;
    float sq = v0*v0 + v1*v1 + v2*v2;
    #pragma unroll
    for (int o = 16; o > 0; o >>= 1) {
        s  += __shfl_down_sync(0xffffffffu, s,  o);
        sq += __shfl_down_sync(0xffffffffu, sq, o);
    }
    int w = tid >> 5, l = tid & 31;
    if (l == 0) { red[w] = s; red[w + 8] = sq; }
    __syncthreads();
    if (tid < 32) {
        float ss = (tid < 8) ? red[tid]     : 0.f;
        float qq = (tid < 8) ? red[tid + 8] : 0.f;
        #pragma unroll
        for (int o = 4; o > 0; o >>= 1) {
            ss += __shfl_down_sync(0xffffffffu, ss, o);
            qq += __shfl_down_sync(0xffffffffu, qq, o);
        }
        if (tid == 0) { red[0] = ss; red[1] = qq; }
    }
    __syncthreads();
    float mu   = red[0] * (1.0f / D_MODEL);
    float var  = red[1] * (1.0f / D_MODEL) - mu * mu;
    float rstd = rsqrtf(var + 1e-5f);
    size_t base = (size_t)row * D_MODEL;
    #pragma unroll
    for (int e = 0; e < 3; e++) {
        int idx = tid + e * 256;
        float v = (e == 0) ? v0 : (e == 1) ? v1 : v2;
        float y = (v - mu) * rstd * g[idx] + b[idx];
        __nv_bfloat16 h = __float2bfloat16(y);
        ohi[base + idx] = h;
        olo[base + idx] = __float2bfloat16(y - __bfloat162float(h));
    }
}

// ---------------------------------------------------------------------------
// Fused hi/lo split of all 8 weight matrices (non-transposed, [k][n]).
// ---------------------------------------------------------------------------
struct WPtrs { const float* w[8]; };

__global__ __launch_bounds__(256)
void split_w_kernel(WPtrs p, __nv_bfloat16* __restrict__ base)
{
    int which = blockIdx.y;
    const float* x = p.w[which];
    __nv_bfloat16* hi = base + (size_t)which * 2 * WEL;
    __nv_bfloat16* lo = hi + WEL;
    int i = blockIdx.x * blockDim.x + threadIdx.x;
    if (i >= WEL / 4) return;
    float4 v = ((const float4*)x)[i];
    float va[4] = {v.x, v.y, v.z, v.w};
    __nv_bfloat16 h[4], l[4];
    #pragma unroll
    for (int e = 0; e < 4; e++) {
        h[e] = __float2bfloat16(va[e]);
        l[e] = __float2bfloat16(va[e] - __bfloat162float(h[e]));
    }
    ((__nv_bfloat162*)hi)[i*2]   = __nv_bfloat162(h[0], h[1]);
    ((__nv_bfloat162*)hi)[i*2+1] = __nv_bfloat162(h[2], h[3]);
    ((__nv_bfloat162*)lo)[i*2]   = __nv_bfloat162(l[0], l[1]);
    ((__nv_bfloat162*)lo)[i*2+1] = __nv_bfloat162(l[2], l[3]);
}

// ---------------------------------------------------------------------------
// Batched split-bf16 HMMA GEMM. blockIdx.z selects the job; up to 4 jobs
// per launch so independent GEMMs' waves interleave (kills the per-launch
// tail). Inner loop identical to R12.
// NPASS=3: C = Ahi*Whi + Ahi*Wlo + Alo*Whi ; NPASS=1: C = Ahi*Whi
// mode 0: fp32 row-major; mode 1: bf16 head layout; mode 2: bf16 hi/lo head.
// ---------------------------------------------------------------------------
#define AS_TYPE  (128 * 40 * 2)        /* 10240 */
#define AS_STAGE (2 * AS_TYPE)         /* 20480 */
#define BS_TYPE  (32 * 136 * 2)        /* 8704  */
#define BS_STAGE (2 * BS_TYPE)         /* 17408 */
#define BS_BASE  (2 * AS_STAGE)        /* 40960 */
#define GSMEM    (BS_BASE + 2 * BS_STAGE)  /* 75776 */
#define NCHUNK   (D_MODEL / 32)        /* 24 */

struct GemmBatch {
    const __nv_bfloat16* Ahi[4];
    const __nv_bfloat16* Alo[4];
    const __nv_bfloat16* Whi[4];
    const __nv_bfloat16* Wlo[4];
    const float*         bias[4];
    float*               Cf[4];
    __nv_bfloat16*       Ch[4];
    __nv_bfloat16*       Cl[4];
};

template<int NPASS>
__device__ __forceinline__ void gemm_load_chunk(
    uint32_t smb, int st, int k0, int bm, int bn, int tid,
    const __nv_bfloat16* __restrict__ Ahi, const __nv_bfloat16* __restrict__ Alo,
    const __nv_bfloat16* __restrict__ Whi, const __nv_bfloat16* __restrict__ Wlo)
{
    int ar = tid >> 2;            // 0..31
    int ac = (tid & 3) * 8;       // 0,8,16,24
    int br = tid >> 4;            // 0..7
    int bc = (tid & 15) * 8;      // 0..120
    #pragma unroll
    for (int rr = 0; rr < 4; rr++) {
        int r = ar + rr * 32;
        uint32_t dst = smb + st * AS_STAGE + (r * 40 + ac) * 2;
        cp16(dst, &Ahi[(size_t)(bm + r) * D_MODEL + k0 + ac]);
        if (NPASS == 3)
            cp16(dst + AS_TYPE, &Alo[(size_t)(bm + r) * D_MODEL + k0 + ac]);
    }
    #pragma unroll
    for (int rr = 0; rr < 4; rr++) {
        int r = br + rr * 8;
        uint32_t dst = smb + BS_BASE + st * BS_STAGE + (r * 136 + bc) * 2;
        cp16(dst, &Whi[(size_t)(k0 + r) * D_MODEL + bn + bc]);
        if (NPASS == 3)
            cp16(dst + BS_TYPE, &Wlo[(size_t)(k0 + r) * D_MODEL + bn + bc]);
    }
    cp_commit();
}

template<int NPASS>
__global__ __launch_bounds__(128, 2)
void gemm_bf16(GemmBatch jb, int mode)
{
    extern __shared__ char smg[];
    uint32_t smb = smem_u32(smg);

    int z = blockIdx.z;
    const __nv_bfloat16* __restrict__ Ahi = jb.Ahi[z];
    const __nv_bfloat16* __restrict__ Alo = jb.Alo[z];
    const __nv_bfloat16* __restrict__ Whi = jb.Whi[z];
    const __nv_bfloat16* __restrict__ Wlo = jb.Wlo[z];
    const float* __restrict__ bias = jb.bias[z];

    int tid  = threadIdx.x;
    int warp = tid >> 5, lane = tid & 31;
    int wm = (warp >> 1) * 64;   // 0,64
    int wn = (warp & 1) * 64;    // 0,64
    int bm = blockIdx.y * 128, bn = blockIdx.x * 128;

    float acc[4][8][4] = {};     // [mi][nj][frag] : warp tile 64x64

    gemm_load_chunk<NPASS>(smb, 0, 0, bm, bn, tid, Ahi, Alo, Whi, Wlo);

    #pragma unroll 1
    for (int ch = 0; ch < NCHUNK; ch++) {
        int st = ch & 1;
        if (ch + 1 < NCHUNK) {
            gemm_load_chunk<NPASS>(smb, (ch + 1) & 1, (ch + 1) * 32, bm, bn, tid,
                                   Ahi, Alo, Whi, Wlo);
            cp_wait<1>();
        } else {
            cp_wait<0>();
        }
        __syncthreads();

        #pragma unroll
        for (int kk = 0; kk < 32; kk += 16) {
            uint32_t ah[4][4], al[4][4];
            uint32_t bh[8][2], bl[8][2];
            #pragma unroll
            for (int mi = 0; mi < 4; mi++) {
                uint32_t aoff = ((wm + mi * 16 + (lane & 15)) * 40 +
                                 kk + (lane >> 4) * 8) * 2;
                ldsm_x4(ah[mi], smb + st * AS_STAGE + aoff);
                if (NPASS == 3)
                    ldsm_x4(al[mi], smb + st * AS_STAGE + AS_TYPE + aoff);
            }
            #pragma unroll
            for (int nj2 = 0; nj2 < 4; nj2++) {
                uint32_t r4[4];
                uint32_t boff = ((kk + (lane & 15)) * 136 +
                                 wn + nj2 * 16 + (lane >> 4) * 8) * 2;
                ldsm_x4_t(r4, smb + BS_BASE + st * BS_STAGE + boff);
                bh[nj2*2+0][0] = r4[0]; bh[nj2*2+0][1] = r4[1];
                bh[nj2*2+1][0] = r4[2]; bh[nj2*2+1][1] = r4[3];
                if (NPASS == 3) {
                    ldsm_x4_t(r4, smb + BS_BASE + st * BS_STAGE + BS_TYPE + boff);
                    bl[nj2*2+0][0] = r4[0]; bl[nj2*2+0][1] = r4[1];
                    bl[nj2*2+1][0] = r4[2]; bl[nj2*2+1][1] = r4[3];
                }
            }
            #pragma unroll
            for (int mi = 0; mi < 4; mi++)
                #pragma unroll
                for (int nj = 0; nj < 8; nj++) {
                    mma_bf16(acc[mi][nj], ah[mi], bh[nj]);
                    if (NPASS == 3) {
                        mma_bf16(acc[mi][nj], ah[mi], bl[nj]);
                        mma_bf16(acc[mi][nj], al[mi], bh[nj]);
                    }
                }
        }
        __syncthreads();
    }

    // Epilogue
    float* __restrict__ Cf = jb.Cf[z];
    __nv_bfloat16* __restrict__ Ch = jb.Ch[z];
    __nv_bfloat16* __restrict__ Cl = jb.Cl[z];
    #pragma unroll
    for (int mi = 0; mi < 4; mi++) {
        #pragma unroll
        for (int nj = 0; nj < 8; nj++) {
            int row0 = bm + wm + mi * 16 + (lane >> 2);
            int col  = bn + wn + nj * 8 + (lane & 3) * 2;
            float b0 = bias[col], b1 = bias[col + 1];
            #pragma unroll
            for (int half = 0; half < 2; half++) {
                int row = row0 + half * 8;
                float v0 = acc[mi][nj][half * 2 + 0] + b0;
                float v1 = acc[mi][nj][half * 2 + 1] + b1;
                if (mode == 0) {
                    float2 v = make_float2(v0, v1);
                    *(float2*)&Cf[(size_t)row * D_MODEL + col] = v;
                } else {
                    int bb = row >> 10;
                    int n  = row & (SEQ - 1);
                    int h  = col >> 6;
                    int dh = col & 63;
                    size_t idx = (((size_t)(bb * HEADS + h)) * SEQ + n) * DH + dh;
                    if (mode == 1) {
                        *(uint32_t*)&Ch[idx] = pack_bf2(v0, v1);
                    } else {
                        float h0 = __bfloat162float(__float2bfloat16(v0));
                        float h1 = __bfloat162float(__float2bfloat16(v1));
                        *(uint32_t*)&Ch[idx] = pack_bf2(h0, h1);
                        *(uint32_t*)&Cl[idx] = pack_bf2(v0 - h0, v1 - h1);
                    }
                }
            }
        }
    }
}

// ---------------------------------------------------------------------------
// HMMA flash attention, 128 threads, 4 warps of m32, batched over z=2.
// ---------------------------------------------------------------------------
#define APAD 72

struct AttnBatch {
    const __nv_bfloat16* Q[2];
    const __nv_bfloat16* K[2];
    const __nv_bfloat16* Vh[2];
    const __nv_bfloat16* Vl[2];
    __nv_bfloat16*       Ohi[2];
    __nv_bfloat16*       Olo[2];
};

__global__ __launch_bounds__(128, 2)
void attn_hmma(AttnBatch ab)
{
    __shared__ __nv_bfloat16 Qs[128][APAD];
    __shared__ __nv_bfloat16 Ks[64][APAD];
    __shared__ __nv_bfloat16 Vh[64][APAD];
    __shared__ __nv_bfloat16 Vl[64][APAD];

    int z = blockIdx.z;
    int tid = threadIdx.x, warp = tid >> 5, lane = tid & 31;
    int bh = blockIdx.y;
    int q0 = blockIdx.x * 128;
    const __nv_bfloat16* Qp  = ab.Q[z]  + (size_t)bh * SEQ * DH + (size_t)q0 * DH;
    const __nv_bfloat16* Kp  = ab.K[z]  + (size_t)bh * SEQ * DH;
    const __nv_bfloat16* Vhq = ab.Vh[z] + (size_t)bh * SEQ * DH;
    const __nv_bfloat16* Vlq = ab.Vl[z] + (size_t)bh * SEQ * DH;

    #pragma unroll
    for (int i = tid; i < 128 * 64 / 8; i += 128) {
        int r = i >> 3, c = (i & 7) * 8;
        *(uint4*)&Qs[r][c] = *(const uint4*)&Qp[(size_t)r * DH + c];
    }

    int wm = warp * 32;
    float mst[2][2], lst[2][2];
    #pragma unroll
    for (int mi = 0; mi < 2; mi++) {
        mst[mi][0] = -INFINITY; mst[mi][1] = -INFINITY;
        lst[mi][0] = 0.f;       lst[mi][1] = 0.f;
    }
    float o[2][8][4] = {};

    #pragma unroll 1
    for (int kv0 = 0; kv0 < SEQ; kv0 += 64) {
        #pragma unroll
        for (int i = tid; i < 64 * 64 / 8; i += 128) {
            int r = i >> 3, c = (i & 7) * 8;
            size_t gi = (size_t)(kv0 + r) * DH + c;
            *(uint4*)&Ks[r][c] = *(const uint4*)&Kp[gi];
            *(uint4*)&Vh[r][c] = *(const uint4*)&Vhq[gi];
            *(uint4*)&Vl[r][c] = *(const uint4*)&Vlq[gi];
        }
        __syncthreads();

        float s[2][8][4] = {};
        #pragma unroll
        for (int d = 0; d < 64; d += 16) {
            uint32_t a0[4], a1[4];
            uint32_t acol = (d + (lane >> 4) * 8);
            ldsm_x4(a0, smem_u32(&Qs[wm +      (lane & 15)][acol]));
            ldsm_x4(a1, smem_u32(&Qs[wm + 16 + (lane & 15)][acol]));
            #pragma unroll
            for (int g = 0; g < 4; g++) {
                uint32_t r4[4];
                ldsm_x4(r4, smem_u32(&Ks[g * 16 + (lane & 15)][acol]));
                uint32_t b0[2] = {r4[0], r4[2]};
                uint32_t b1[2] = {r4[1], r4[3]};
                mma_bf16(s[0][2 * g],     a0, b0);
                mma_bf16(s[0][2 * g + 1], a0, b1);
                mma_bf16(s[1][2 * g],     a1, b0);
                mma_bf16(s[1][2 * g + 1], a1, b1);
            }
        }

        uint32_t phh[2][4][4], pll[2][4][4];
        #pragma unroll
        for (int mi = 0; mi < 2; mi++) {
            float tm0 = -INFINITY, tm1 = -INFINITY;
            #pragma unroll
            for (int f = 0; f < 8; f++) {
                #pragma unroll
                for (int j = 0; j < 4; j++) s[mi][f][j] *= 0.125f;
                tm0 = fmaxf(tm0, fmaxf(s[mi][f][0], s[mi][f][1]));
                tm1 = fmaxf(tm1, fmaxf(s[mi][f][2], s[mi][f][3]));
            }
            tm0 = fmaxf(tm0, __shfl_xor_sync(0xffffffffu, tm0, 1));
            tm0 = fmaxf(tm0, __shfl_xor_sync(0xffffffffu, tm0, 2));
            tm1 = fmaxf(tm1, __shfl_xor_sync(0xffffffffu, tm1, 1));
            tm1 = fmaxf(tm1, __shfl_xor_sync(0xffffffffu, tm1, 2));
            float mn0 = fmaxf(mst[mi][0], tm0), mn1 = fmaxf(mst[mi][1], tm1);
            float al0 = __expf(mst[mi][0] - mn0), al1 = __expf(mst[mi][1] - mn1);
            mst[mi][0] = mn0; mst[mi][1] = mn1;

            float rs0 = 0.f, rs1 = 0.f;
            #pragma unroll
            for (int f = 0; f < 8; f++) {
                s[mi][f][0] = __expf(s[mi][f][0] - mn0);
                s[mi][f][1] = __expf(s[mi][f][1] - mn0);
                s[mi][f][2] = __expf(s[mi][f][2] - mn1);
                s[mi][f][3] = __expf(s[mi][f][3] - mn1);
                rs0 += s[mi][f][0] + s[mi][f][1];
                rs1 += s[mi][f][2] + s[mi][f][3];
            }
            rs0 += __shfl_xor_sync(0xffffffffu, rs0, 1);
            rs0 += __shfl_xor_sync(0xffffffffu, rs0, 2);
            rs1 += __shfl_xor_sync(0xffffffffu, rs1, 1);
            rs1 += __shfl_xor_sync(0xffffffffu, rs1, 2);
            lst[mi][0] = lst[mi][0] * al0 + rs0;
            lst[mi][1] = lst[mi][1] * al1 + rs1;

            #pragma unroll
            for (int f = 0; f < 8; f++) {
                o[mi][f][0] *= al0; o[mi][f][1] *= al0;
                o[mi][f][2] *= al1; o[mi][f][3] *= al1;
            }

            #pragma unroll
            for (int c = 0; c < 4; c++) {
                float* f0 = s[mi][2 * c];
                float* f1 = s[mi][2 * c + 1];
                float v8[8] = {f0[0], f0[1], f0[2], f0[3],
                               f1[0], f1[1], f1[2], f1[3]};
                float hi8[8];
                #pragma unroll
                for (int e = 0; e < 8; e++)
                    hi8[e] = __bfloat162float(__float2bfloat16(v8[e]));
                phh[mi][c][0] = pack_bf2(hi8[0], hi8[1]);
                phh[mi][c][1] = pack_bf2(hi8[2], hi8[3]);
                phh[mi][c][2] = pack_bf2(hi8[4], hi8[5]);
                phh[mi][c][3] = pack_bf2(hi8[6], hi8[7]);
                pll[mi][c][0] = pack_bf2(v8[0] - hi8[0], v8[1] - hi8[1]);
                pll[mi][c][1] = pack_bf2(v8[2] - hi8[2], v8[3] - hi8[3]);
                pll[mi][c][2] = pack_bf2(v8[4] - hi8[4], v8[5] - hi8[5]);
                pll[mi][c][3] = pack_bf2(v8[6] - hi8[6], v8[7] - hi8[7]);
            }
        }

        #pragma unroll
        for (int c = 0; c < 4; c++) {
            #pragma unroll
            for (int g = 0; g < 4; g++) {
                uint32_t r4[4];
                int rowv = c * 16 + (lane & 15);
                int colv = g * 16 + (lane >> 4) * 8;
                ldsm_x4_t(r4, smem_u32(&Vh[rowv][colv]));
                uint32_t b0[2] = {r4[0], r4[1]};
                uint32_t b1[2] = {r4[2], r4[3]};
                #pragma unroll
                for (int mi = 0; mi < 2; mi++) {
                    mma_bf16(o[mi][2 * g],     phh[mi][c], b0);
                    mma_bf16(o[mi][2 * g + 1], phh[mi][c], b1);
                    mma_bf16(o[mi][2 * g],     pll[mi][c], b0);
                    mma_bf16(o[mi][2 * g + 1], pll[mi][c], b1);
                }
                ldsm_x4_t(r4, smem_u32(&Vl[rowv][colv]));
                uint32_t c0[2] = {r4[0], r4[1]};
                uint32_t c1[2] = {r4[2], r4[3]};
                #pragma unroll
                for (int mi = 0; mi < 2; mi++) {
                    mma_bf16(o[mi][2 * g],     phh[mi][c], c0);
                    mma_bf16(o[mi][2 * g + 1], phh[mi][c], c1);
                }
            }
        }
        __syncthreads();
    }

    int b = bh / HEADS, h = bh % HEADS;
    __nv_bfloat16* __restrict__ Ohi = ab.Ohi[z];
    __nv_bfloat16* __restrict__ Olo = ab.Olo[z];
    #pragma unroll
    for (int mi = 0; mi < 2; mi++) {
        float inv0 = 1.f / lst[mi][0], inv1 = 1.f / lst[mi][1];
        int r0 = q0 + wm + mi * 16 + (lane >> 2);
        #pragma unroll
        for (int g = 0; g < 8; g++) {
            int col = h * DH + g * 8 + (lane & 3) * 2;
            #pragma unroll
            for (int half = 0; half < 2; half++) {
                int n = r0 + half * 8;
                float inv = half ? inv1 : inv0;
                float v0 = o[mi][g][half * 2 + 0] * inv;
                float v1 = o[mi][g][half * 2 + 1] * inv;
                float h0 = __bfloat162float(__float2bfloat16(v0));
                float h1 = __bfloat162float(__float2bfloat16(v1));
                size_t idx = ((size_t)(b * SEQ + n)) * D_MODEL + col;
                *(uint32_t*)&Ohi[idx] = pack_bf2(h0, h1);
                *(uint32_t*)&Olo[idx] = pack_bf2(v0 - h0, v1 - h1);
            }
        }
    }
}

// ---------------------------------------------------------------------------
extern "C" void kernel_launch(void* const* d_in, const int* in_sizes, int n_in,
                              void* d_out, int out_size)
{
    const float* x1    = (const float*)d_in[0];
    const float* x2    = (const float*)d_in[1];
    const float* ln1_g = (const float*)d_in[2];
    const float* ln1_b = (const float*)d_in[3];
    const float* ln2_g = (const float*)d_in[4];
    const float* ln2_b = (const float*)d_in[5];
    WPtrs wp;
    wp.w[0] = (const float*)d_in[6];
    wp.w[1] = (const float*)d_in[8];
    wp.w[2] = (const float*)d_in[10];
    wp.w[3] = (const float*)d_in[12];
    wp.w[4] = (const float*)d_in[14];
    wp.w[5] = (const float*)d_in[16];
    wp.w[6] = (const float*)d_in[18];
    wp.w[7] = (const float*)d_in[20];
    const float* b_in[8] = {
        (const float*)d_in[7],  (const float*)d_in[9],  (const float*)d_in[11],
        (const float*)d_in[13], (const float*)d_in[15], (const float*)d_in[17],
        (const float*)d_in[19], (const float*)d_in[21]
    };
    float* out = (float*)d_out;

    __nv_bfloat16* bf;
    cudaGetSymbolAddress((void**)&bf, g_bf16);

    __nv_bfloat16* m1hi = bf;
    __nv_bfloat16* m1lo = m1hi + ELEMS;
    __nv_bfloat16* m2hi = m1lo + ELEMS;
    __nv_bfloat16* m2lo = m2hi + ELEMS;
    __nv_bfloat16* q1   = m2lo + ELEMS;
    __nv_bfloat16* k1   = q1 + ELEMS;
    __nv_bfloat16* vh1  = k1 + ELEMS;
    __nv_bfloat16* vl1  = vh1 + ELEMS;
    __nv_bfloat16* q2   = vl1 + ELEMS;
    __nv_bfloat16* k2   = q2 + ELEMS;
    __nv_bfloat16* vh2  = k2 + ELEMS;
    __nv_bfloat16* vl2  = vh2 + ELEMS;
    __nv_bfloat16* a1hi = vl2 + ELEMS;
    __nv_bfloat16* a1lo = a1hi + ELEMS;
    __nv_bfloat16* a2hi = a1lo + ELEMS;
    __nv_bfloat16* a2lo = a2hi + ELEMS;
    __nv_bfloat16* wbase = a2lo + ELEMS;

    dim3 wg((WEL/4 + 255)/256, 8);
    split_w_kernel<<<wg, 256>>>(wp, wbase);

    ln_split_kernel<<<ROWS, 256>>>(x1, ln1_g, ln1_b, m1hi, m1lo);
    ln_split_kernel<<<ROWS, 256>>>(x2, ln2_g, ln2_b, m2hi, m2lo);

    cudaFuncSetAttribute(gemm_bf16<1>, cudaFuncAttributeMaxDynamicSharedMemorySize,
                         GSMEM);
    cudaFuncSetAttribute(gemm_bf16<3>, cudaFuncAttributeMaxDynamicSharedMemorySize,
                         GSMEM);

    // --- Q,K projections: 4 jobs in one launch (1-pass) ---
    {
        GemmBatch jb = {};
        int widx[4] = {0, 1, 3, 4};                    // wq1, wk1, wq2, wk2
        __nv_bfloat16* outs[4] = {q1, k1, q2, k2};
        for (int j = 0; j < 4; j++) {
            int i = widx[j];
            jb.Ahi[j]  = (i < 3) ? m1hi : m2hi;
            jb.Alo[j]  = nullptr;
            jb.Whi[j]  = wbase + (size_t)i * 2 * WEL;
            jb.Wlo[j]  = nullptr;
            jb.bias[j] = b_in[i];
            jb.Ch[j]   = outs[j];
        }
        dim3 gq(D_MODEL / 128, ROWS / 128, 4);         // (6, 64, 4)
        gemm_bf16<1><<<gq, 128, GSMEM>>>(jb, 1);
    }

    // --- V projections: 2 jobs in one launch (3-pass, hi/lo out) ---
    {
        GemmBatch jb = {};
        jb.Ahi[0] = m1hi; jb.Alo[0] = m1lo;
        jb.Whi[0] = wbase + 2ull * 2 * WEL; jb.Wlo[0] = wbase + 2ull * 2 * WEL + WEL;
        jb.bias[0] = b_in[2]; jb.Ch[0] = vh1; jb.Cl[0] = vl1;
        jb.Ahi[1] = m2hi; jb.Alo[1] = m2lo;
        jb.Whi[1] = wbase + 5ull * 2 * WEL; jb.Wlo[1] = wbase + 5ull * 2 * WEL + WEL;
        jb.bias[1] = b_in[5]; jb.Ch[1] = vh2; jb.Cl[1] = vl2;
        dim3 gv(D_MODEL / 128, ROWS / 128, 2);         // (6, 64, 2)
        gemm_bf16<3><<<gv, 128, GSMEM>>>(jb, 2);
    }

    // --- Attention: both directions in one launch ---
    {
        AttnBatch ab;
        ab.Q[0] = q1; ab.K[0] = k2; ab.Vh[0] = vh2; ab.Vl[0] = vl2;
        ab.Ohi[0] = a1hi; ab.Olo[0] = a1lo;
        ab.Q[1] = q2; ab.K[1] = k1; ab.Vh[1] = vh1; ab.Vl[1] = vl1;
        ab.Ohi[1] = a2hi; ab.Olo[1] = a2lo;
        dim3 ag(SEQ / 128, BATCH * HEADS, 2);          // (8, 96, 2)
        attn_hmma<<<ag, 128>>>(ab);
    }

    // --- Output projections: 2 jobs in one launch (3-pass, fp32 out) ---
    {
        GemmBatch jb = {};
        jb.Ahi[0] = a1hi; jb.Alo[0] = a1lo;
        jb.Whi[0] = wbase + 6ull * 2 * WEL; jb.Wlo[0] = wbase + 6ull * 2 * WEL + WEL;
        jb.bias[0] = b_in[6]; jb.Cf[0] = out;
        jb.Ahi[1] = a2hi; jb.Alo[1] = a2lo;
        jb.Whi[1] = wbase + 7ull * 2 * WEL; jb.Wlo[1] = wbase + 7ull * 2 * WEL + WEL;
        jb.bias[1] = b_in[7]; jb.Cf[1] = out + ELEMS;
        dim3 go(D_MODEL / 128, ROWS / 128, 2);         // (6, 64, 2)
        gemm_bf16<3><<<go, 128, GSMEM>>>(jb, 0);
    }
}

// round 14
// speedup vs baseline: 1.2724x; 1.2724x over previous
#include <cuda_runtime.h>
#include <cuda_bf16.h>
#include <stdint.h>
#include <math.h>

#define D_MODEL 768
#define HEADS   12
#define DH      64
#define SEQ     1024
#define BATCH   8
#define ROWS    (BATCH*SEQ)        /* 8192 */
#define ELEMS   (ROWS*D_MODEL)     /* 6291456 */
#define WEL     (D_MODEL*D_MODEL)  /* 589824 */

__device__ __nv_bfloat16 g_bf16[16ull * ELEMS + 16ull * WEL];

// ---------------------------------------------------------------------------
// PTX helpers
// ---------------------------------------------------------------------------
__device__ __forceinline__ uint32_t smem_u32(const void* p) {
    return (uint32_t)__cvta_generic_to_shared(p);
}
__device__ __forceinline__ void ldsm_x4(uint32_t r[4], uint32_t addr) {
    asm volatile("ldmatrix.sync.aligned.m8n8.x4.shared.b16 {%0,%1,%2,%3}, [%4];"
                 : "=r"(r[0]), "=r"(r[1]), "=r"(r[2]), "=r"(r[3]) : "r"(addr));
}
__device__ __forceinline__ void ldsm_x4_t(uint32_t r[4], uint32_t addr) {
    asm volatile("ldmatrix.sync.aligned.m8n8.x4.trans.shared.b16 {%0,%1,%2,%3}, [%4];"
                 : "=r"(r[0]), "=r"(r[1]), "=r"(r[2]), "=r"(r[3]) : "r"(addr));
}
__device__ __forceinline__ void mma_bf16(float d[4], const uint32_t a[4],
                                         const uint32_t b[2]) {
    asm volatile(
        "mma.sync.aligned.m16n8k16.row.col.f32.bf16.bf16.f32 "
        "{%0,%1,%2,%3}, {%4,%5,%6,%7}, {%8,%9}, {%0,%1,%2,%3};"
        : "+f"(d[0]), "+f"(d[1]), "+f"(d[2]), "+f"(d[3])
        : "r"(a[0]), "r"(a[1]), "r"(a[2]), "r"(a[3]), "r"(b[0]), "r"(b[1]));
}
__device__ __forceinline__ uint32_t pack_bf2(float a, float b) {
    __nv_bfloat162 t = __floats2bfloat162_rn(a, b);
    return *(uint32_t*)&t;
}
__device__ __forceinline__ void cp16(uint32_t s, const void* g) {
    asm volatile("cp.async.cg.shared.global [%0], [%1], 16;" :: "r"(s), "l"(g));
}
__device__ __forceinline__ void cp_commit() {
    asm volatile("cp.async.commit_group;" ::: "memory");
}
template<int N> __device__ __forceinline__ void cp_wait() {
    asm volatile("cp.async.wait_group %0;" :: "n"(N) : "memory");
}

// ---------------------------------------------------------------------------
// LayerNorm fused with hi/lo bf16 split. One block per row, 256 threads.
// ---------------------------------------------------------------------------
__global__ __launch_bounds__(256)
void ln_split_kernel(const float* __restrict__ x, const float* __restrict__ g,
                     const float* __restrict__ b,
                     __nv_bfloat16* __restrict__ ohi, __nv_bfloat16* __restrict__ olo)
{
    __shared__ float red[16];
    int row = blockIdx.x;
    int tid = threadIdx.x;
    const float* xp = x + (size_t)row * D_MODEL;
    float v0 = xp[tid], v1 = xp[tid + 256], v2 = xp[tid + 512];
    float s  = v0 + v1 + v2;
    float sq = v0*v0 + v1*v1 + v2*v2;
    #pragma unroll
    for (int o = 16; o > 0; o >>= 1) {
        s  += __shfl_down_sync(0xffffffffu, s,  o);
        sq += __shfl_down_sync(0xffffffffu, sq, o);
    }
    int w = tid >> 5, l = tid & 31;
    if (l == 0) { red[w] = s; red[w + 8] = sq; }
    __syncthreads();
    if (tid < 32) {
        float ss = (tid < 8) ? red[tid]     : 0.f;
        float qq = (tid < 8) ? red[tid + 8] : 0.f;
        #pragma unroll
        for (int o = 4; o > 0; o >>= 1) {
            ss += __shfl_down_sync(0xffffffffu, ss, o);
            qq += __shfl_down_sync(0xffffffffu, qq, o);
        }
        if (tid == 0) { red[0] = ss; red[1] = qq; }
    }
    __syncthreads();
    float mu   = red[0] * (1.0f / D_MODEL);
    float var  = red[1] * (1.0f / D_MODEL) - mu * mu;
    float rstd = rsqrtf(var + 1e-5f);
    size_t base = (size_t)row * D_MODEL;
    #pragma unroll
    for (int e = 0; e < 3; e++) {
        int idx = tid + e * 256;
        float v = (e == 0) ? v0 : (e == 1) ? v1 : v2;
        float y = (v - mu) * rstd * g[idx] + b[idx];
        __nv_bfloat16 h = __float2bfloat16(y);
        ohi[base + idx] = h;
        olo[base + idx] = __float2bfloat16(y - __bfloat162float(h));
    }
}

// ---------------------------------------------------------------------------
// Fused hi/lo split of all 8 weight matrices (non-transposed, [k][n]).
// ---------------------------------------------------------------------------
struct WPtrs { const float* w[8]; };

__global__ __launch_bounds__(256)
void split_w_kernel(WPtrs p, __nv_bfloat16* __restrict__ base)
{
    int which = blockIdx.y;
    const float* x = p.w[which];
    __nv_bfloat16* hi = base + (size_t)which * 2 * WEL;
    __nv_bfloat16* lo = hi + WEL;
    int i = blockIdx.x * blockDim.x + threadIdx.x;
    if (i >= WEL / 4) return;
    float4 v = ((const float4*)x)[i];
    float va[4] = {v.x, v.y, v.z, v.w};
    __nv_bfloat16 h[4], l[4];
    #pragma unroll
    for (int e = 0; e < 4; e++) {
        h[e] = __float2bfloat16(va[e]);
        l[e] = __float2bfloat16(va[e] - __bfloat162float(h[e]));
    }
    ((__nv_bfloat162*)hi)[i*2]   = __nv_bfloat162(h[0], h[1]);
    ((__nv_bfloat162*)hi)[i*2+1] = __nv_bfloat162(h[2], h[3]);
    ((__nv_bfloat162*)lo)[i*2]   = __nv_bfloat162(l[0], l[1]);
    ((__nv_bfloat162*)lo)[i*2+1] = __nv_bfloat162(l[2], l[3]);
}

// ---------------------------------------------------------------------------
// Split-bf16 HMMA GEMM (R12 structure: one job per launch).
// NPASS=3: C = Ahi*Whi + Ahi*Wlo + Alo*Whi ; NPASS=1: C = Ahi*Whi
// mode 0: fp32 row-major; mode 1: bf16 head layout; mode 2: bf16 hi/lo head.
// ---------------------------------------------------------------------------
#define AS_TYPE  (128 * 40 * 2)        /* 10240 */
#define AS_STAGE (2 * AS_TYPE)         /* 20480 */
#define BS_TYPE  (32 * 136 * 2)        /* 8704  */
#define BS_STAGE (2 * BS_TYPE)         /* 17408 */
#define BS_BASE  (2 * AS_STAGE)        /* 40960 */
#define GSMEM    (BS_BASE + 2 * BS_STAGE)  /* 75776 */
#define NCHUNK   (D_MODEL / 32)        /* 24 */

template<int NPASS>
__device__ __forceinline__ void gemm_load_chunk(
    uint32_t smb, int st, int k0, int bm, int bn, int tid,
    const __nv_bfloat16* __restrict__ Ahi, const __nv_bfloat16* __restrict__ Alo,
    const __nv_bfloat16* __restrict__ Whi, const __nv_bfloat16* __restrict__ Wlo)
{
    int ar = tid >> 2;            // 0..31
    int ac = (tid & 3) * 8;       // 0,8,16,24
    int br = tid >> 4;            // 0..7
    int bc = (tid & 15) * 8;      // 0..120
    #pragma unroll
    for (int rr = 0; rr < 4; rr++) {
        int r = ar + rr * 32;
        uint32_t dst = smb + st * AS_STAGE + (r * 40 + ac) * 2;
        cp16(dst, &Ahi[(size_t)(bm + r) * D_MODEL + k0 + ac]);
        if (NPASS == 3)
            cp16(dst + AS_TYPE, &Alo[(size_t)(bm + r) * D_MODEL + k0 + ac]);
    }
    #pragma unroll
    for (int rr = 0; rr < 4; rr++) {
        int r = br + rr * 8;
        uint32_t dst = smb + BS_BASE + st * BS_STAGE + (r * 136 + bc) * 2;
        cp16(dst, &Whi[(size_t)(k0 + r) * D_MODEL + bn + bc]);
        if (NPASS == 3)
            cp16(dst + BS_TYPE, &Wlo[(size_t)(k0 + r) * D_MODEL + bn + bc]);
    }
    cp_commit();
}

template<int NPASS>
__global__ __launch_bounds__(128, 2)
void gemm_bf16(const __nv_bfloat16* __restrict__ Ahi, const __nv_bfloat16* __restrict__ Alo,
               const __nv_bfloat16* __restrict__ Whi, const __nv_bfloat16* __restrict__ Wlo,
               const float* __restrict__ bias,
               float* __restrict__ Cf, __nv_bfloat16* __restrict__ Ch,
               __nv_bfloat16* __restrict__ Cl, int mode)
{
    extern __shared__ char smg[];
    uint32_t smb = smem_u32(smg);

    int tid  = threadIdx.x;
    int warp = tid >> 5, lane = tid & 31;
    int wm = (warp >> 1) * 64;   // 0,64
    int wn = (warp & 1) * 64;    // 0,64
    int bm = blockIdx.y * 128, bn = blockIdx.x * 128;

    float acc[4][8][4] = {};     // [mi][nj][frag] : warp tile 64x64

    gemm_load_chunk<NPASS>(smb, 0, 0, bm, bn, tid, Ahi, Alo, Whi, Wlo);

    #pragma unroll 1
    for (int ch = 0; ch < NCHUNK; ch++) {
        int st = ch & 1;
        if (ch + 1 < NCHUNK) {
            gemm_load_chunk<NPASS>(smb, (ch + 1) & 1, (ch + 1) * 32, bm, bn, tid,
                                   Ahi, Alo, Whi, Wlo);
            cp_wait<1>();
        } else {
            cp_wait<0>();
        }
        __syncthreads();

        #pragma unroll
        for (int kk = 0; kk < 32; kk += 16) {
            uint32_t ah[4][4], al[4][4];
            uint32_t bh[8][2], bl[8][2];
            #pragma unroll
            for (int mi = 0; mi < 4; mi++) {
                uint32_t aoff = ((wm + mi * 16 + (lane & 15)) * 40 +
                                 kk + (lane >> 4) * 8) * 2;
                ldsm_x4(ah[mi], smb + st * AS_STAGE + aoff);
                if (NPASS == 3)
                    ldsm_x4(al[mi], smb + st * AS_STAGE + AS_TYPE + aoff);
            }
            #pragma unroll
            for (int nj2 = 0; nj2 < 4; nj2++) {
                uint32_t r4[4];
                uint32_t boff = ((kk + (lane & 15)) * 136 +
                                 wn + nj2 * 16 + (lane >> 4) * 8) * 2;
                ldsm_x4_t(r4, smb + BS_BASE + st * BS_STAGE + boff);
                bh[nj2*2+0][0] = r4[0]; bh[nj2*2+0][1] = r4[1];
                bh[nj2*2+1][0] = r4[2]; bh[nj2*2+1][1] = r4[3];
                if (NPASS == 3) {
                    ldsm_x4_t(r4, smb + BS_BASE + st * BS_STAGE + BS_TYPE + boff);
                    bl[nj2*2+0][0] = r4[0]; bl[nj2*2+0][1] = r4[1];
                    bl[nj2*2+1][0] = r4[2]; bl[nj2*2+1][1] = r4[3];
                }
            }
            #pragma unroll
            for (int mi = 0; mi < 4; mi++)
                #pragma unroll
                for (int nj = 0; nj < 8; nj++) {
                    mma_bf16(acc[mi][nj], ah[mi], bh[nj]);
                    if (NPASS == 3) {
                        mma_bf16(acc[mi][nj], ah[mi], bl[nj]);
                        mma_bf16(acc[mi][nj], al[mi], bh[nj]);
                    }
                }
        }
        __syncthreads();
    }

    // Epilogue
    #pragma unroll
    for (int mi = 0; mi < 4; mi++) {
        #pragma unroll
        for (int nj = 0; nj < 8; nj++) {
            int row0 = bm + wm + mi * 16 + (lane >> 2);
            int col  = bn + wn + nj * 8 + (lane & 3) * 2;
            float b0 = bias[col], b1 = bias[col + 1];
            #pragma unroll
            for (int half = 0; half < 2; half++) {
                int row = row0 + half * 8;
                float v0 = acc[mi][nj][half * 2 + 0] + b0;
                float v1 = acc[mi][nj][half * 2 + 1] + b1;
                if (mode == 0) {
                    float2 v = make_float2(v0, v1);
                    *(float2*)&Cf[(size_t)row * D_MODEL + col] = v;
                } else {
                    int bb = row >> 10;
                    int n  = row & (SEQ - 1);
                    int h  = col >> 6;
                    int dh = col & 63;
                    size_t idx = (((size_t)(bb * HEADS + h)) * SEQ + n) * DH + dh;
                    if (mode == 1) {
                        *(uint32_t*)&Ch[idx] = pack_bf2(v0, v1);
                    } else {
                        float h0 = __bfloat162float(__float2bfloat16(v0));
                        float h1 = __bfloat162float(__float2bfloat16(v1));
                        *(uint32_t*)&Ch[idx] = pack_bf2(h0, h1);
                        *(uint32_t*)&Cl[idx] = pack_bf2(v0 - h0, v1 - h1);
                    }
                }
            }
        }
    }
}

// ---------------------------------------------------------------------------
// HMMA flash attention, 128 threads, 4 warps of m32.
// K/Vh/Vl staged via 2-stage cp.async pipeline in dynamic smem.
// Compute identical to R12 (bit-identical numerics).
// ---------------------------------------------------------------------------
#define APAD 72
#define AQ_BYTES  (128 * APAD * 2)     /* 18432 */
#define AKV_BYTES (64 * APAD * 2)      /* 9216  */
#define ASTAGE    (3 * AKV_BYTES)      /* 27648 */
#define ASMEM     (AQ_BYTES + 2 * ASTAGE)  /* 73728 */

__device__ __forceinline__ void attn_load_kv(
    uint32_t smb, int st, int kv0, int tid,
    const __nv_bfloat16* __restrict__ Kp,
    const __nv_bfloat16* __restrict__ Vhq,
    const __nv_bfloat16* __restrict__ Vlq)
{
    uint32_t base = smb + AQ_BYTES + st * ASTAGE;
    #pragma unroll
    for (int j = 0; j < 4; j++) {
        int i = tid + j * 128;            // 0..511
        int r = i >> 3, c = (i & 7) * 8;
        size_t gi = (size_t)(kv0 + r) * DH + c;
        uint32_t off = (r * APAD + c) * 2;
        cp16(base + off,                 &Kp[gi]);
        cp16(base + AKV_BYTES + off,     &Vhq[gi]);
        cp16(base + 2 * AKV_BYTES + off, &Vlq[gi]);
    }
    cp_commit();
}

__global__ __launch_bounds__(128, 2)
void attn_hmma(const __nv_bfloat16* __restrict__ Q, const __nv_bfloat16* __restrict__ K,
               const __nv_bfloat16* __restrict__ Vhp, const __nv_bfloat16* __restrict__ Vlp,
               __nv_bfloat16* __restrict__ Ohi, __nv_bfloat16* __restrict__ Olo)
{
    extern __shared__ char sma[];
    uint32_t smb = smem_u32(sma);
    __nv_bfloat16* Qs = (__nv_bfloat16*)sma;   // [128][APAD]

    int tid = threadIdx.x, warp = tid >> 5, lane = tid & 31;
    int bh = blockIdx.y;
    int q0 = blockIdx.x * 128;
    const __nv_bfloat16* Qp  = Q   + (size_t)bh * SEQ * DH + (size_t)q0 * DH;
    const __nv_bfloat16* Kp  = K   + (size_t)bh * SEQ * DH;
    const __nv_bfloat16* Vhq = Vhp + (size_t)bh * SEQ * DH;
    const __nv_bfloat16* Vlq = Vlp + (size_t)bh * SEQ * DH;

    #pragma unroll
    for (int i = tid; i < 128 * 64 / 8; i += 128) {
        int r = i >> 3, c = (i & 7) * 8;
        *(uint4*)&Qs[r * APAD + c] = *(const uint4*)&Qp[(size_t)r * DH + c];
    }

    // prologue: stage 0 <- kv chunk 0
    attn_load_kv(smb, 0, 0, tid, Kp, Vhq, Vlq);

    int wm = warp * 32;
    float mst[2][2], lst[2][2];
    #pragma unroll
    for (int mi = 0; mi < 2; mi++) {
        mst[mi][0] = -INFINITY; mst[mi][1] = -INFINITY;
        lst[mi][0] = 0.f;       lst[mi][1] = 0.f;
    }
    float o[2][8][4] = {};

    #pragma unroll 1
    for (int kv0 = 0; kv0 < SEQ; kv0 += 64) {
        int st = (kv0 >> 6) & 1;
        uint32_t kb = smb + AQ_BYTES + st * ASTAGE;
        uint32_t vhb = kb + AKV_BYTES;
        uint32_t vlb = kb + 2 * AKV_BYTES;

        if (kv0 + 64 < SEQ) {
            attn_load_kv(smb, st ^ 1, kv0 + 64, tid, Kp, Vhq, Vlq);
            cp_wait<1>();
        } else {
            cp_wait<0>();
        }
        __syncthreads();

        float s[2][8][4] = {};
        #pragma unroll
        for (int d = 0; d < 64; d += 16) {
            uint32_t a0[4], a1[4];
            int acol = d + (lane >> 4) * 8;
            ldsm_x4(a0, smb + ((wm +      (lane & 15)) * APAD + acol) * 2);
            ldsm_x4(a1, smb + ((wm + 16 + (lane & 15)) * APAD + acol) * 2);
            #pragma unroll
            for (int g = 0; g < 4; g++) {
                uint32_t r4[4];
                ldsm_x4(r4, kb + ((g * 16 + (lane & 15)) * APAD + acol) * 2);
                uint32_t b0[2] = {r4[0], r4[2]};
                uint32_t b1[2] = {r4[1], r4[3]};
                mma_bf16(s[0][2 * g],     a0, b0);
                mma_bf16(s[0][2 * g + 1], a0, b1);
                mma_bf16(s[1][2 * g],     a1, b0);
                mma_bf16(s[1][2 * g + 1], a1, b1);
            }
        }

        uint32_t phh[2][4][4], pll[2][4][4];
        #pragma unroll
        for (int mi = 0; mi < 2; mi++) {
            float tm0 = -INFINITY, tm1 = -INFINITY;
            #pragma unroll
            for (int f = 0; f < 8; f++) {
                #pragma unroll
                for (int j = 0; j < 4; j++) s[mi][f][j] *= 0.125f;
                tm0 = fmaxf(tm0, fmaxf(s[mi][f][0], s[mi][f][1]));
                tm1 = fmaxf(tm1, fmaxf(s[mi][f][2], s[mi][f][3]));
            }
            tm0 = fmaxf(tm0, __shfl_xor_sync(0xffffffffu, tm0, 1));
            tm0 = fmaxf(tm0, __shfl_xor_sync(0xffffffffu, tm0, 2));
            tm1 = fmaxf(tm1, __shfl_xor_sync(0xffffffffu, tm1, 1));
            tm1 = fmaxf(tm1, __shfl_xor_sync(0xffffffffu, tm1, 2));
            float mn0 = fmaxf(mst[mi][0], tm0), mn1 = fmaxf(mst[mi][1], tm1);
            float al0 = __expf(mst[mi][0] - mn0), al1 = __expf(mst[mi][1] - mn1);
            mst[mi][0] = mn0; mst[mi][1] = mn1;

            float rs0 = 0.f, rs1 = 0.f;
            #pragma unroll
            for (int f = 0; f < 8; f++) {
                s[mi][f][0] = __expf(s[mi][f][0] - mn0);
                s[mi][f][1] = __expf(s[mi][f][1] - mn0);
                s[mi][f][2] = __expf(s[mi][f][2] - mn1);
                s[mi][f][3] = __expf(s[mi][f][3] - mn1);
                rs0 += s[mi][f][0] + s[mi][f][1];
                rs1 += s[mi][f][2] + s[mi][f][3];
            }
            rs0 += __shfl_xor_sync(0xffffffffu, rs0, 1);
            rs0 += __shfl_xor_sync(0xffffffffu, rs0, 2);
            rs1 += __shfl_xor_sync(0xffffffffu, rs1, 1);
            rs1 += __shfl_xor_sync(0xffffffffu, rs1, 2);
            lst[mi][0] = lst[mi][0] * al0 + rs0;
            lst[mi][1] = lst[mi][1] * al1 + rs1;

            #pragma unroll
            for (int f = 0; f < 8; f++) {
                o[mi][f][0] *= al0; o[mi][f][1] *= al0;
                o[mi][f][2] *= al1; o[mi][f][3] *= al1;
            }

            #pragma unroll
            for (int c = 0; c < 4; c++) {
                float* f0 = s[mi][2 * c];
                float* f1 = s[mi][2 * c + 1];
                float v8[8] = {f0[0], f0[1], f0[2], f0[3],
                               f1[0], f1[1], f1[2], f1[3]};
                float hi8[8];
                #pragma unroll
                for (int e = 0; e < 8; e++)
                    hi8[e] = __bfloat162float(__float2bfloat16(v8[e]));
                phh[mi][c][0] = pack_bf2(hi8[0], hi8[1]);
                phh[mi][c][1] = pack_bf2(hi8[2], hi8[3]);
                phh[mi][c][2] = pack_bf2(hi8[4], hi8[5]);
                phh[mi][c][3] = pack_bf2(hi8[6], hi8[7]);
                pll[mi][c][0] = pack_bf2(v8[0] - hi8[0], v8[1] - hi8[1]);
                pll[mi][c][1] = pack_bf2(v8[2] - hi8[2], v8[3] - hi8[3]);
                pll[mi][c][2] = pack_bf2(v8[4] - hi8[4], v8[5] - hi8[5]);
                pll[mi][c][3] = pack_bf2(v8[6] - hi8[6], v8[7] - hi8[7]);
            }
        }

        #pragma unroll
        for (int c = 0; c < 4; c++) {
            #pragma unroll
            for (int g = 0; g < 4; g++) {
                uint32_t r4[4];
                uint32_t voff = ((c * 16 + (lane & 15)) * APAD +
                                 g * 16 + (lane >> 4) * 8) * 2;
                ldsm_x4_t(r4, vhb + voff);
                uint32_t b0[2] = {r4[0], r4[1]};
                uint32_t b1[2] = {r4[2], r4[3]};
                #pragma unroll
                for (int mi = 0; mi < 2; mi++) {
                    mma_bf16(o[mi][2 * g],     phh[mi][c], b0);
                    mma_bf16(o[mi][2 * g + 1], phh[mi][c], b1);
                    mma_bf16(o[mi][2 * g],     pll[mi][c], b0);
                    mma_bf16(o[mi][2 * g + 1], pll[mi][c], b1);
                }
                ldsm_x4_t(r4, vlb + voff);
                uint32_t c0[2] = {r4[0], r4[1]};
                uint32_t c1[2] = {r4[2], r4[3]};
                #pragma unroll
                for (int mi = 0; mi < 2; mi++) {
                    mma_bf16(o[mi][2 * g],     phh[mi][c], c0);
                    mma_bf16(o[mi][2 * g + 1], phh[mi][c], c1);
                }
            }
        }
        __syncthreads();
    }

    int b = bh / HEADS, h = bh % HEADS;
    #pragma unroll
    for (int mi = 0; mi < 2; mi++) {
        float inv0 = 1.f / lst[mi][0], inv1 = 1.f / lst[mi][1];
        int r0 = q0 + wm + mi * 16 + (lane >> 2);
        #pragma unroll
        for (int g = 0; g < 8; g++) {
            int col = h * DH + g * 8 + (lane & 3) * 2;
            #pragma unroll
            for (int half = 0; half < 2; half++) {
                int n = r0 + half * 8;
                float inv = half ? inv1 : inv0;
                float v0 = o[mi][g][half * 2 + 0] * inv;
                float v1 = o[mi][g][half * 2 + 1] * inv;
                float h0 = __bfloat162float(__float2bfloat16(v0));
                float h1 = __bfloat162float(__float2bfloat16(v1));
                size_t idx = ((size_t)(b * SEQ + n)) * D_MODEL + col;
                *(uint32_t*)&Ohi[idx] = pack_bf2(h0, h1);
                *(uint32_t*)&Olo[idx] = pack_bf2(v0 - h0, v1 - h1);
            }
        }
    }
}

// ---------------------------------------------------------------------------
extern "C" void kernel_launch(void* const* d_in, const int* in_sizes, int n_in,
                              void* d_out, int out_size)
{
    const float* x1    = (const float*)d_in[0];
    const float* x2    = (const float*)d_in[1];
    const float* ln1_g = (const float*)d_in[2];
    const float* ln1_b = (const float*)d_in[3];
    const float* ln2_g = (const float*)d_in[4];
    const float* ln2_b = (const float*)d_in[5];
    WPtrs wp;
    wp.w[0] = (const float*)d_in[6];
    wp.w[1] = (const float*)d_in[8];
    wp.w[2] = (const float*)d_in[10];
    wp.w[3] = (const float*)d_in[12];
    wp.w[4] = (const float*)d_in[14];
    wp.w[5] = (const float*)d_in[16];
    wp.w[6] = (const float*)d_in[18];
    wp.w[7] = (const float*)d_in[20];
    const float* b_in[8] = {
        (const float*)d_in[7],  (const float*)d_in[9],  (const float*)d_in[11],
        (const float*)d_in[13], (const float*)d_in[15], (const float*)d_in[17],
        (const float*)d_in[19], (const float*)d_in[21]
    };
    float* out = (float*)d_out;

    __nv_bfloat16* bf;
    cudaGetSymbolAddress((void**)&bf, g_bf16);

    __nv_bfloat16* m1hi = bf;
    __nv_bfloat16* m1lo = m1hi + ELEMS;
    __nv_bfloat16* m2hi = m1lo + ELEMS;
    __nv_bfloat16* m2lo = m2hi + ELEMS;
    __nv_bfloat16* q1   = m2lo + ELEMS;
    __nv_bfloat16* k1   = q1 + ELEMS;
    __nv_bfloat16* vh1  = k1 + ELEMS;
    __nv_bfloat16* vl1  = vh1 + ELEMS;
    __nv_bfloat16* q2   = vl1 + ELEMS;
    __nv_bfloat16* k2   = q2 + ELEMS;
    __nv_bfloat16* vh2  = k2 + ELEMS;
    __nv_bfloat16* vl2  = vh2 + ELEMS;
    __nv_bfloat16* a1hi = vl2 + ELEMS;
    __nv_bfloat16* a1lo = a1hi + ELEMS;
    __nv_bfloat16* a2hi = a1lo + ELEMS;
    __nv_bfloat16* a2lo = a2hi + ELEMS;
    __nv_bfloat16* wbase = a2lo + ELEMS;

    dim3 wg((WEL/4 + 255)/256, 8);
    split_w_kernel<<<wg, 256>>>(wp, wbase);

    ln_split_kernel<<<ROWS, 256>>>(x1, ln1_g, ln1_b, m1hi, m1lo);
    ln_split_kernel<<<ROWS, 256>>>(x2, ln2_g, ln2_b, m2hi, m2lo);

    cudaFuncSetAttribute(gemm_bf16<1>, cudaFuncAttributeMaxDynamicSharedMemorySize,
                         GSMEM);
    cudaFuncSetAttribute(gemm_bf16<3>, cudaFuncAttributeMaxDynamicSharedMemorySize,
                         GSMEM);
    cudaFuncSetAttribute(attn_hmma, cudaFuncAttributeMaxDynamicSharedMemorySize,
                         ASMEM);

    dim3 gg(D_MODEL / 128, ROWS / 128);   // (6, 64)

    // Q,K projections: single-pass bf16
    int qk[4] = {0, 1, 3, 4};   // wq1, wk1, wq2, wk2
    __nv_bfloat16* qk_out[4] = {q1, k1, q2, k2};
    for (int j = 0; j < 4; j++) {
        int i = qk[j];
        __nv_bfloat16* ahi = (i < 3) ? m1hi : m2hi;
        gemm_bf16<1><<<gg, 128, GSMEM>>>(ahi, nullptr,
                               wbase + (size_t)i*2*WEL, nullptr,
                               b_in[i], nullptr, qk_out[j], nullptr, 1);
    }
    // V projections: 3-pass split, hi/lo output
    gemm_bf16<3><<<gg, 128, GSMEM>>>(m1hi, m1lo,
                           wbase + 2ull*2*WEL, wbase + 2ull*2*WEL + WEL,
                           b_in[2], nullptr, vh1, vl1, 2);
    gemm_bf16<3><<<gg, 128, GSMEM>>>(m2hi, m2lo,
                           wbase + 5ull*2*WEL, wbase + 5ull*2*WEL + WEL,
                           b_in[5], nullptr, vh2, vl2, 2);

    dim3 ag(SEQ / 128, BATCH * HEADS);    // (8, 96)
    attn_hmma<<<ag, 128, ASMEM>>>(q1, k2, vh2, vl2, a1hi, a1lo);
    attn_hmma<<<ag, 128, ASMEM>>>(q2, k1, vh1, vl1, a2hi, a2lo);

    gemm_bf16<3><<<gg, 128, GSMEM>>>(a1hi, a1lo, wbase + 6ull*2*WEL, wbase + 6ull*2*WEL + WEL,
                           b_in[6], out, nullptr, nullptr, 0);
    gemm_bf16<3><<<gg, 128, GSMEM>>>(a2hi, a2lo, wbase + 7ull*2*WEL, wbase + 7ull*2*WEL + WEL,
                           b_in[7], out + ELEMS, nullptr, nullptr, 0);
}

// round 15
// speedup vs baseline: 1.3032x; 1.0242x over previous
#include <cuda_runtime.h>
#include <cuda_bf16.h>
#include <stdint.h>
#include <math.h>

#define D_MODEL 768
#define HEADS   12
#define DH      64
#define SEQ     1024
#define BATCH   8
#define ROWS    (BATCH*SEQ)        /* 8192 */
#define ELEMS   (ROWS*D_MODEL)     /* 6291456 */
#define WEL     (D_MODEL*D_MODEL)  /* 589824 */

__device__ __nv_bfloat16 g_bf16[16ull * ELEMS + 16ull * WEL];

// ---------------------------------------------------------------------------
// PTX helpers
// ---------------------------------------------------------------------------
__device__ __forceinline__ uint32_t smem_u32(const void* p) {
    return (uint32_t)__cvta_generic_to_shared(p);
}
__device__ __forceinline__ void ldsm_x4(uint32_t r[4], uint32_t addr) {
    asm volatile("ldmatrix.sync.aligned.m8n8.x4.shared.b16 {%0,%1,%2,%3}, [%4];"
                 : "=r"(r[0]), "=r"(r[1]), "=r"(r[2]), "=r"(r[3]) : "r"(addr));
}
__device__ __forceinline__ void ldsm_x4_t(uint32_t r[4], uint32_t addr) {
    asm volatile("ldmatrix.sync.aligned.m8n8.x4.trans.shared.b16 {%0,%1,%2,%3}, [%4];"
                 : "=r"(r[0]), "=r"(r[1]), "=r"(r[2]), "=r"(r[3]) : "r"(addr));
}
__device__ __forceinline__ void mma_bf16(float d[4], const uint32_t a[4],
                                         const uint32_t b[2]) {
    asm volatile(
        "mma.sync.aligned.m16n8k16.row.col.f32.bf16.bf16.f32 "
        "{%0,%1,%2,%3}, {%4,%5,%6,%7}, {%8,%9}, {%0,%1,%2,%3};"
        : "+f"(d[0]), "+f"(d[1]), "+f"(d[2]), "+f"(d[3])
        : "r"(a[0]), "r"(a[1]), "r"(a[2]), "r"(a[3]), "r"(b[0]), "r"(b[1]));
}
__device__ __forceinline__ uint32_t pack_bf2(float a, float b) {
    __nv_bfloat162 t = __floats2bfloat162_rn(a, b);
    return *(uint32_t*)&t;
}
__device__ __forceinline__ void cp16(uint32_t s, const void* g) {
    asm volatile("cp.async.cg.shared.global [%0], [%1], 16;" :: "r"(s), "l"(g));
}
__device__ __forceinline__ void cp_commit() {
    asm volatile("cp.async.commit_group;" ::: "memory");
}
template<int N> __device__ __forceinline__ void cp_wait() {
    asm volatile("cp.async.wait_group %0;" :: "n"(N) : "memory");
}

// ---------------------------------------------------------------------------
// LayerNorm fused with hi/lo bf16 split. One block per row, 256 threads.
// ---------------------------------------------------------------------------
__global__ __launch_bounds__(256)
void ln_split_kernel(const float* __restrict__ x, const float* __restrict__ g,
                     const float* __restrict__ b,
                     __nv_bfloat16* __restrict__ ohi, __nv_bfloat16* __restrict__ olo)
{
    __shared__ float red[16];
    int row = blockIdx.x;
    int tid = threadIdx.x;
    const float* xp = x + (size_t)row * D_MODEL;
    float v0 = xp[tid], v1 = xp[tid + 256], v2 = xp[tid + 512];
    float s  = v0 + v1 + v2;
    float sq = v0*v0 + v1*v1 + v2*v2;
    #pragma unroll
    for (int o = 16; o > 0; o >>= 1) {
        s  += __shfl_down_sync(0xffffffffu, s,  o);
        sq += __shfl_down_sync(0xffffffffu, sq, o);
    }
    int w = tid >> 5, l = tid & 31;
    if (l == 0) { red[w] = s; red[w + 8] = sq; }
    __syncthreads();
    if (tid < 32) {
        float ss = (tid < 8) ? red[tid]     : 0.f;
        float qq = (tid < 8) ? red[tid + 8] : 0.f;
        #pragma unroll
        for (int o = 4; o > 0; o >>= 1) {
            ss += __shfl_down_sync(0xffffffffu, ss, o);
            qq += __shfl_down_sync(0xffffffffu, qq, o);
        }
        if (tid == 0) { red[0] = ss; red[1] = qq; }
    }
    __syncthreads();
    float mu   = red[0] * (1.0f / D_MODEL);
    float var  = red[1] * (1.0f / D_MODEL) - mu * mu;
    float rstd = rsqrtf(var + 1e-5f);
    size_t base = (size_t)row * D_MODEL;
    #pragma unroll
    for (int e = 0; e < 3; e++) {
        int idx = tid + e * 256;
        float v = (e == 0) ? v0 : (e == 1) ? v1 : v2;
        float y = (v - mu) * rstd * g[idx] + b[idx];
        __nv_bfloat16 h = __float2bfloat16(y);
        ohi[base + idx] = h;
        olo[base + idx] = __float2bfloat16(y - __bfloat162float(h));
    }
}

// ---------------------------------------------------------------------------
// Fused hi/lo split of all 8 weight matrices (non-transposed, [k][n]).
// ---------------------------------------------------------------------------
struct WPtrs { const float* w[8]; };

__global__ __launch_bounds__(256)
void split_w_kernel(WPtrs p, __nv_bfloat16* __restrict__ base)
{
    int which = blockIdx.y;
    const float* x = p.w[which];
    __nv_bfloat16* hi = base + (size_t)which * 2 * WEL;
    __nv_bfloat16* lo = hi + WEL;
    int i = blockIdx.x * blockDim.x + threadIdx.x;
    if (i >= WEL / 4) return;
    float4 v = ((const float4*)x)[i];
    float va[4] = {v.x, v.y, v.z, v.w};
    __nv_bfloat16 h[4], l[4];
    #pragma unroll
    for (int e = 0; e < 4; e++) {
        h[e] = __float2bfloat16(va[e]);
        l[e] = __float2bfloat16(va[e] - __bfloat162float(h[e]));
    }
    ((__nv_bfloat162*)hi)[i*2]   = __nv_bfloat162(h[0], h[1]);
    ((__nv_bfloat162*)hi)[i*2+1] = __nv_bfloat162(h[2], h[3]);
    ((__nv_bfloat162*)lo)[i*2]   = __nv_bfloat162(l[0], l[1]);
    ((__nv_bfloat162*)lo)[i*2+1] = __nv_bfloat162(l[2], l[3]);
}

// ---------------------------------------------------------------------------
// GEMM smem layout (shared by both GEMM kernels)
// ---------------------------------------------------------------------------
#define AS_TYPE  (128 * 40 * 2)        /* 10240 */
#define AS_STAGE (2 * AS_TYPE)         /* 20480 */
#define BS_TYPE  (32 * 136 * 2)        /* 8704  */
#define BS_STAGE (2 * BS_TYPE)         /* 17408 */
#define BS_BASE  (2 * AS_STAGE)        /* 40960 */
#define GSMEM    (BS_BASE + 2 * BS_STAGE)  /* 75776 */
#define NCHUNK   (D_MODEL / 32)        /* 24 */

template<int NPASS>
__device__ __forceinline__ void gemm_load_chunk(
    uint32_t smb, int st, int k0, int bm, int bn, int tid,
    const __nv_bfloat16* __restrict__ Ahi, const __nv_bfloat16* __restrict__ Alo,
    const __nv_bfloat16* __restrict__ Whi, const __nv_bfloat16* __restrict__ Wlo)
{
    int ar = tid >> 2;            // 0..31
    int ac = (tid & 3) * 8;       // 0,8,16,24
    int br = tid >> 4;            // 0..7
    int bc = (tid & 15) * 8;      // 0..120
    #pragma unroll
    for (int rr = 0; rr < 4; rr++) {
        int r = ar + rr * 32;
        uint32_t dst = smb + st * AS_STAGE + (r * 40 + ac) * 2;
        cp16(dst, &Ahi[(size_t)(bm + r) * D_MODEL + k0 + ac]);
        if (NPASS == 3)
            cp16(dst + AS_TYPE, &Alo[(size_t)(bm + r) * D_MODEL + k0 + ac]);
    }
    #pragma unroll
    for (int rr = 0; rr < 4; rr++) {
        int r = br + rr * 8;
        uint32_t dst = smb + BS_BASE + st * BS_STAGE + (r * 136 + bc) * 2;
        cp16(dst, &Whi[(size_t)(k0 + r) * D_MODEL + bn + bc]);
        if (NPASS == 3)
            cp16(dst + BS_TYPE, &Wlo[(size_t)(k0 + r) * D_MODEL + bn + bc]);
    }
    cp_commit();
}

// ---------------------------------------------------------------------------
// Batched 1-pass QK GEMM: 4 jobs via blockIdx.z (measured faster in R13).
// C = Ahi*Whi + bias, bf16 head-layout output.
// ---------------------------------------------------------------------------
struct QKJobs {
    const __nv_bfloat16* A[4];
    const __nv_bfloat16* W[4];
    const float*         bias[4];
    __nv_bfloat16*       C[4];
};

__global__ __launch_bounds__(128, 2)
void gemm_qk(QKJobs jb)
{
    extern __shared__ char smg[];
    uint32_t smb = smem_u32(smg);

    int z = blockIdx.z;
    const __nv_bfloat16* __restrict__ A = jb.A[z];
    const __nv_bfloat16* __restrict__ W = jb.W[z];
    const float* __restrict__ bias = jb.bias[z];
    __nv_bfloat16* __restrict__ C = jb.C[z];

    int tid  = threadIdx.x;
    int warp = tid >> 5, lane = tid & 31;
    int wm = (warp >> 1) * 64;
    int wn = (warp & 1) * 64;
    int bm = blockIdx.y * 128, bn = blockIdx.x * 128;

    float acc[4][8][4] = {};

    gemm_load_chunk<1>(smb, 0, 0, bm, bn, tid, A, nullptr, W, nullptr);

    #pragma unroll 1
    for (int ch = 0; ch < NCHUNK; ch++) {
        int st = ch & 1;
        if (ch + 1 < NCHUNK) {
            gemm_load_chunk<1>(smb, (ch + 1) & 1, (ch + 1) * 32, bm, bn, tid,
                               A, nullptr, W, nullptr);
            cp_wait<1>();
        } else {
            cp_wait<0>();
        }
        __syncthreads();

        #pragma unroll
        for (int kk = 0; kk < 32; kk += 16) {
            uint32_t ah[4][4];
            uint32_t bh[8][2];
            #pragma unroll
            for (int mi = 0; mi < 4; mi++) {
                uint32_t aoff = ((wm + mi * 16 + (lane & 15)) * 40 +
                                 kk + (lane >> 4) * 8) * 2;
                ldsm_x4(ah[mi], smb + st * AS_STAGE + aoff);
            }
            #pragma unroll
            for (int nj2 = 0; nj2 < 4; nj2++) {
                uint32_t r4[4];
                uint32_t boff = ((kk + (lane & 15)) * 136 +
                                 wn + nj2 * 16 + (lane >> 4) * 8) * 2;
                ldsm_x4_t(r4, smb + BS_BASE + st * BS_STAGE + boff);
                bh[nj2*2+0][0] = r4[0]; bh[nj2*2+0][1] = r4[1];
                bh[nj2*2+1][0] = r4[2]; bh[nj2*2+1][1] = r4[3];
            }
            #pragma unroll
            for (int mi = 0; mi < 4; mi++)
                #pragma unroll
                for (int nj = 0; nj < 8; nj++)
                    mma_bf16(acc[mi][nj], ah[mi], bh[nj]);
        }
        __syncthreads();
    }

    #pragma unroll
    for (int mi = 0; mi < 4; mi++) {
        #pragma unroll
        for (int nj = 0; nj < 8; nj++) {
            int row0 = bm + wm + mi * 16 + (lane >> 2);
            int col  = bn + wn + nj * 8 + (lane & 3) * 2;
            float b0 = bias[col], b1 = bias[col + 1];
            #pragma unroll
            for (int half = 0; half < 2; half++) {
                int row = row0 + half * 8;
                float v0 = acc[mi][nj][half * 2 + 0] + b0;
                float v1 = acc[mi][nj][half * 2 + 1] + b1;
                int bb = row >> 10;
                int n  = row & (SEQ - 1);
                int h  = col >> 6;
                int dh = col & 63;
                size_t idx = (((size_t)(bb * HEADS + h)) * SEQ + n) * DH + dh;
                *(uint32_t*)&C[idx] = pack_bf2(v0, v1);
            }
        }
    }
}

// ---------------------------------------------------------------------------
// 3-pass split-bf16 GEMM, single job per launch (job-pure, R14 structure).
// mode 0: fp32 row-major; mode 2: bf16 hi/lo head layout.
// ---------------------------------------------------------------------------
__global__ __launch_bounds__(128, 2)
void gemm3(const __nv_bfloat16* __restrict__ Ahi, const __nv_bfloat16* __restrict__ Alo,
           const __nv_bfloat16* __restrict__ Whi, const __nv_bfloat16* __restrict__ Wlo,
           const float* __restrict__ bias,
           float* __restrict__ Cf, __nv_bfloat16* __restrict__ Ch,
           __nv_bfloat16* __restrict__ Cl, int mode)
{
    extern __shared__ char smg[];
    uint32_t smb = smem_u32(smg);

    int tid  = threadIdx.x;
    int warp = tid >> 5, lane = tid & 31;
    int wm = (warp >> 1) * 64;
    int wn = (warp & 1) * 64;
    int bm = blockIdx.y * 128, bn = blockIdx.x * 128;

    float acc[4][8][4] = {};

    gemm_load_chunk<3>(smb, 0, 0, bm, bn, tid, Ahi, Alo, Whi, Wlo);

    #pragma unroll 1
    for (int ch = 0; ch < NCHUNK; ch++) {
        int st = ch & 1;
        if (ch + 1 < NCHUNK) {
            gemm_load_chunk<3>(smb, (ch + 1) & 1, (ch + 1) * 32, bm, bn, tid,
                               Ahi, Alo, Whi, Wlo);
            cp_wait<1>();
        } else {
            cp_wait<0>();
        }
        __syncthreads();

        #pragma unroll
        for (int kk = 0; kk < 32; kk += 16) {
            uint32_t ah[4][4], al[4][4];
            uint32_t bh[8][2], bl[8][2];
            #pragma unroll
            for (int mi = 0; mi < 4; mi++) {
                uint32_t aoff = ((wm + mi * 16 + (lane & 15)) * 40 +
                                 kk + (lane >> 4) * 8) * 2;
                ldsm_x4(ah[mi], smb + st * AS_STAGE + aoff);
                ldsm_x4(al[mi], smb + st * AS_STAGE + AS_TYPE + aoff);
            }
            #pragma unroll
            for (int nj2 = 0; nj2 < 4; nj2++) {
                uint32_t r4[4];
                uint32_t boff = ((kk + (lane & 15)) * 136 +
                                 wn + nj2 * 16 + (lane >> 4) * 8) * 2;
                ldsm_x4_t(r4, smb + BS_BASE + st * BS_STAGE + boff);
                bh[nj2*2+0][0] = r4[0]; bh[nj2*2+0][1] = r4[1];
                bh[nj2*2+1][0] = r4[2]; bh[nj2*2+1][1] = r4[3];
                ldsm_x4_t(r4, smb + BS_BASE + st * BS_STAGE + BS_TYPE + boff);
                bl[nj2*2+0][0] = r4[0]; bl[nj2*2+0][1] = r4[1];
                bl[nj2*2+1][0] = r4[2]; bl[nj2*2+1][1] = r4[3];
            }
            #pragma unroll
            for (int mi = 0; mi < 4; mi++)
                #pragma unroll
                for (int nj = 0; nj < 8; nj++) {
                    mma_bf16(acc[mi][nj], ah[mi], bh[nj]);
                    mma_bf16(acc[mi][nj], ah[mi], bl[nj]);
                    mma_bf16(acc[mi][nj], al[mi], bh[nj]);
                }
        }
        __syncthreads();
    }

    #pragma unroll
    for (int mi = 0; mi < 4; mi++) {
        #pragma unroll
        for (int nj = 0; nj < 8; nj++) {
            int row0 = bm + wm + mi * 16 + (lane >> 2);
            int col  = bn + wn + nj * 8 + (lane & 3) * 2;
            float b0 = bias[col], b1 = bias[col + 1];
            #pragma unroll
            for (int half = 0; half < 2; half++) {
                int row = row0 + half * 8;
                float v0 = acc[mi][nj][half * 2 + 0] + b0;
                float v1 = acc[mi][nj][half * 2 + 1] + b1;
                if (mode == 0) {
                    float2 v = make_float2(v0, v1);
                    *(float2*)&Cf[(size_t)row * D_MODEL + col] = v;
                } else {
                    int bb = row >> 10;
                    int n  = row & (SEQ - 1);
                    int h  = col >> 6;
                    int dh = col & 63;
                    size_t idx = (((size_t)(bb * HEADS + h)) * SEQ + n) * DH + dh;
                    float h0 = __bfloat162float(__float2bfloat16(v0));
                    float h1 = __bfloat162float(__float2bfloat16(v1));
                    *(uint32_t*)&Ch[idx] = pack_bf2(h0, h1);
                    *(uint32_t*)&Cl[idx] = pack_bf2(v0 - h0, v1 - h1);
                }
            }
        }
    }
}

// ---------------------------------------------------------------------------
// HMMA flash attention, 128 threads, 4 warps of m32.
// K/Vh/Vl staged via 3-stage cp.async pipeline in dynamic smem.
// ---------------------------------------------------------------------------
#define APAD 72
#define AQ_BYTES  (128 * APAD * 2)     /* 18432 */
#define AKV_BYTES (64 * APAD * 2)      /* 9216  */
#define ASTAGE    (3 * AKV_BYTES)      /* 27648 */
#define NSTAGES   3
#define ASMEM     (AQ_BYTES + NSTAGES * ASTAGE)  /* 101376 */

__device__ __forceinline__ void attn_load_kv(
    uint32_t smb, int st, int kv0, int tid,
    const __nv_bfloat16* __restrict__ Kp,
    const __nv_bfloat16* __restrict__ Vhq,
    const __nv_bfloat16* __restrict__ Vlq)
{
    uint32_t base = smb + AQ_BYTES + st * ASTAGE;
    #pragma unroll
    for (int j = 0; j < 4; j++) {
        int i = tid + j * 128;            // 0..511
        int r = i >> 3, c = (i & 7) * 8;
        size_t gi = (size_t)(kv0 + r) * DH + c;
        uint32_t off = (r * APAD + c) * 2;
        cp16(base + off,                 &Kp[gi]);
        cp16(base + AKV_BYTES + off,     &Vhq[gi]);
        cp16(base + 2 * AKV_BYTES + off, &Vlq[gi]);
    }
    cp_commit();
}

__global__ __launch_bounds__(128, 2)
void attn_hmma(const __nv_bfloat16* __restrict__ Q, const __nv_bfloat16* __restrict__ K,
               const __nv_bfloat16* __restrict__ Vhp, const __nv_bfloat16* __restrict__ Vlp,
               __nv_bfloat16* __restrict__ Ohi, __nv_bfloat16* __restrict__ Olo)
{
    extern __shared__ char sma[];
    uint32_t smb = smem_u32(sma);
    __nv_bfloat16* Qs = (__nv_bfloat16*)sma;   // [128][APAD]

    int tid = threadIdx.x, warp = tid >> 5, lane = tid & 31;
    int bh = blockIdx.y;
    int q0 = blockIdx.x * 128;
    const __nv_bfloat16* Qp  = Q   + (size_t)bh * SEQ * DH + (size_t)q0 * DH;
    const __nv_bfloat16* Kp  = K   + (size_t)bh * SEQ * DH;
    const __nv_bfloat16* Vhq = Vhp + (size_t)bh * SEQ * DH;
    const __nv_bfloat16* Vlq = Vlp + (size_t)bh * SEQ * DH;

    #pragma unroll
    for (int i = tid; i < 128 * 64 / 8; i += 128) {
        int r = i >> 3, c = (i & 7) * 8;
        *(uint4*)&Qs[r * APAD + c] = *(const uint4*)&Qp[(size_t)r * DH + c];
    }

    // prologue: prefetch chunks 0 and 1
    attn_load_kv(smb, 0, 0, tid, Kp, Vhq, Vlq);
    attn_load_kv(smb, 1, 64, tid, Kp, Vhq, Vlq);

    int wm = warp * 32;
    float mst[2][2], lst[2][2];
    #pragma unroll
    for (int mi = 0; mi < 2; mi++) {
        mst[mi][0] = -INFINITY; mst[mi][1] = -INFINITY;
        lst[mi][0] = 0.f;       lst[mi][1] = 0.f;
    }
    float o[2][8][4] = {};

    #pragma unroll 1
    for (int kv0 = 0; kv0 < SEQ; kv0 += 64) {
        int ch = kv0 >> 6;
        int st = ch % NSTAGES;
        uint32_t kb = smb + AQ_BYTES + st * ASTAGE;
        uint32_t vhb = kb + AKV_BYTES;
        uint32_t vlb = kb + 2 * AKV_BYTES;

        if (kv0 + 128 < SEQ) {
            attn_load_kv(smb, (ch + 2) % NSTAGES, kv0 + 128, tid, Kp, Vhq, Vlq);
            cp_wait<2>();
        } else if (kv0 + 64 < SEQ) {
            cp_wait<1>();
        } else {
            cp_wait<0>();
        }
        __syncthreads();

        float s[2][8][4] = {};
        #pragma unroll
        for (int d = 0; d < 64; d += 16) {
            uint32_t a0[4], a1[4];
            int acol = d + (lane >> 4) * 8;
            ldsm_x4(a0, smb + ((wm +      (lane & 15)) * APAD + acol) * 2);
            ldsm_x4(a1, smb + ((wm + 16 + (lane & 15)) * APAD + acol) * 2);
            #pragma unroll
            for (int g = 0; g < 4; g++) {
                uint32_t r4[4];
                ldsm_x4(r4, kb + ((g * 16 + (lane & 15)) * APAD + acol) * 2);
                uint32_t b0[2] = {r4[0], r4[2]};
                uint32_t b1[2] = {r4[1], r4[3]};
                mma_bf16(s[0][2 * g],     a0, b0);
                mma_bf16(s[0][2 * g + 1], a0, b1);
                mma_bf16(s[1][2 * g],     a1, b0);
                mma_bf16(s[1][2 * g + 1], a1, b1);
            }
        }

        uint32_t phh[2][4][4], pll[2][4][4];
        #pragma unroll
        for (int mi = 0; mi < 2; mi++) {
            float tm0 = -INFINITY, tm1 = -INFINITY;
            #pragma unroll
            for (int f = 0; f < 8; f++) {
                #pragma unroll
                for (int j = 0; j < 4; j++) s[mi][f][j] *= 0.125f;
                tm0 = fmaxf(tm0, fmaxf(s[mi][f][0], s[mi][f][1]));
                tm1 = fmaxf(tm1, fmaxf(s[mi][f][2], s[mi][f][3]));
            }
            tm0 = fmaxf(tm0, __shfl_xor_sync(0xffffffffu, tm0, 1));
            tm0 = fmaxf(tm0, __shfl_xor_sync(0xffffffffu, tm0, 2));
            tm1 = fmaxf(tm1, __shfl_xor_sync(0xffffffffu, tm1, 1));
            tm1 = fmaxf(tm1, __shfl_xor_sync(0xffffffffu, tm1, 2));
            float mn0 = fmaxf(mst[mi][0], tm0), mn1 = fmaxf(mst[mi][1], tm1);
            float al0 = __expf(mst[mi][0] - mn0), al1 = __expf(mst[mi][1] - mn1);
            mst[mi][0] = mn0; mst[mi][1] = mn1;

            float rs0 = 0.f, rs1 = 0.f;
            #pragma unroll
            for (int f = 0; f < 8; f++) {
                s[mi][f][0] = __expf(s[mi][f][0] - mn0);
                s[mi][f][1] = __expf(s[mi][f][1] - mn0);
                s[mi][f][2] = __expf(s[mi][f][2] - mn1);
                s[mi][f][3] = __expf(s[mi][f][3] - mn1);
                rs0 += s[mi][f][0] + s[mi][f][1];
                rs1 += s[mi][f][2] + s[mi][f][3];
            }
            rs0 += __shfl_xor_sync(0xffffffffu, rs0, 1);
            rs0 += __shfl_xor_sync(0xffffffffu, rs0, 2);
            rs1 += __shfl_xor_sync(0xffffffffu, rs1, 1);
            rs1 += __shfl_xor_sync(0xffffffffu, rs1, 2);
            lst[mi][0] = lst[mi][0] * al0 + rs0;
            lst[mi][1] = lst[mi][1] * al1 + rs1;

            #pragma unroll
            for (int f = 0; f < 8; f++) {
                o[mi][f][0] *= al0; o[mi][f][1] *= al0;
                o[mi][f][2] *= al1; o[mi][f][3] *= al1;
            }

            #pragma unroll
            for (int c = 0; c < 4; c++) {
                float* f0 = s[mi][2 * c];
                float* f1 = s[mi][2 * c + 1];
                float v8[8] = {f0[0], f0[1], f0[2], f0[3],
                               f1[0], f1[1], f1[2], f1[3]};
                float hi8[8];
                #pragma unroll
                for (int e = 0; e < 8; e++)
                    hi8[e] = __bfloat162float(__float2bfloat16(v8[e]));
                phh[mi][c][0] = pack_bf2(hi8[0], hi8[1]);
                phh[mi][c][1] = pack_bf2(hi8[2], hi8[3]);
                phh[mi][c][2] = pack_bf2(hi8[4], hi8[5]);
                phh[mi][c][3] = pack_bf2(hi8[6], hi8[7]);
                pll[mi][c][0] = pack_bf2(v8[0] - hi8[0], v8[1] - hi8[1]);
                pll[mi][c][1] = pack_bf2(v8[2] - hi8[2], v8[3] - hi8[3]);
                pll[mi][c][2] = pack_bf2(v8[4] - hi8[4], v8[5] - hi8[5]);
                pll[mi][c][3] = pack_bf2(v8[6] - hi8[6], v8[7] - hi8[7]);
            }
        }

        #pragma unroll
        for (int c = 0; c < 4; c++) {
            #pragma unroll
            for (int g = 0; g < 4; g++) {
                uint32_t r4[4];
                uint32_t voff = ((c * 16 + (lane & 15)) * APAD +
                                 g * 16 + (lane >> 4) * 8) * 2;
                ldsm_x4_t(r4, vhb + voff);
                uint32_t b0[2] = {r4[0], r4[1]};
                uint32_t b1[2] = {r4[2], r4[3]};
                #pragma unroll
                for (int mi = 0; mi < 2; mi++) {
                    mma_bf16(o[mi][2 * g],     phh[mi][c], b0);
                    mma_bf16(o[mi][2 * g + 1], phh[mi][c], b1);
                    mma_bf16(o[mi][2 * g],     pll[mi][c], b0);
                    mma_bf16(o[mi][2 * g + 1], pll[mi][c], b1);
                }
                ldsm_x4_t(r4, vlb + voff);
                uint32_t c0[2] = {r4[0], r4[1]};
                uint32_t c1[2] = {r4[2], r4[3]};
                #pragma unroll
                for (int mi = 0; mi < 2; mi++) {
                    mma_bf16(o[mi][2 * g],     phh[mi][c], c0);
                    mma_bf16(o[mi][2 * g + 1], phh[mi][c], c1);
                }
            }
        }
        __syncthreads();
    }

    int b = bh / HEADS, h = bh % HEADS;
    #pragma unroll
    for (int mi = 0; mi < 2; mi++) {
        float inv0 = 1.f / lst[mi][0], inv1 = 1.f / lst[mi][1];
        int r0 = q0 + wm + mi * 16 + (lane >> 2);
        #pragma unroll
        for (int g = 0; g < 8; g++) {
            int col = h * DH + g * 8 + (lane & 3) * 2;
            #pragma unroll
            for (int half = 0; half < 2; half++) {
                int n = r0 + half * 8;
                float inv = half ? inv1 : inv0;
                float v0 = o[mi][g][half * 2 + 0] * inv;
                float v1 = o[mi][g][half * 2 + 1] * inv;
                float h0 = __bfloat162float(__float2bfloat16(v0));
                float h1 = __bfloat162float(__float2bfloat16(v1));
                size_t idx = ((size_t)(b * SEQ + n)) * D_MODEL + col;
                *(uint32_t*)&Ohi[idx] = pack_bf2(h0, h1);
                *(uint32_t*)&Olo[idx] = pack_bf2(v0 - h0, v1 - h1);
            }
        }
    }
}

// ---------------------------------------------------------------------------
extern "C" void kernel_launch(void* const* d_in, const int* in_sizes, int n_in,
                              void* d_out, int out_size)
{
    const float* x1    = (const float*)d_in[0];
    const float* x2    = (const float*)d_in[1];
    const float* ln1_g = (const float*)d_in[2];
    const float* ln1_b = (const float*)d_in[3];
    const float* ln2_g = (const float*)d_in[4];
    const float* ln2_b = (const float*)d_in[5];
    WPtrs wp;
    wp.w[0] = (const float*)d_in[6];
    wp.w[1] = (const float*)d_in[8];
    wp.w[2] = (const float*)d_in[10];
    wp.w[3] = (const float*)d_in[12];
    wp.w[4] = (const float*)d_in[14];
    wp.w[5] = (const float*)d_in[16];
    wp.w[6] = (const float*)d_in[18];
    wp.w[7] = (const float*)d_in[20];
    const float* b_in[8] = {
        (const float*)d_in[7],  (const float*)d_in[9],  (const float*)d_in[11],
        (const float*)d_in[13], (const float*)d_in[15], (const float*)d_in[17],
        (const float*)d_in[19], (const float*)d_in[21]
    };
    float* out = (float*)d_out;

    __nv_bfloat16* bf;
    cudaGetSymbolAddress((void**)&bf, g_bf16);

    __nv_bfloat16* m1hi = bf;
    __nv_bfloat16* m1lo = m1hi + ELEMS;
    __nv_bfloat16* m2hi = m1lo + ELEMS;
    __nv_bfloat16* m2lo = m2hi + ELEMS;
    __nv_bfloat16* q1   = m2lo + ELEMS;
    __nv_bfloat16* k1   = q1 + ELEMS;
    __nv_bfloat16* vh1  = k1 + ELEMS;
    __nv_bfloat16* vl1  = vh1 + ELEMS;
    __nv_bfloat16* q2   = vl1 + ELEMS;
    __nv_bfloat16* k2   = q2 + ELEMS;
    __nv_bfloat16* vh2  = k2 + ELEMS;
    __nv_bfloat16* vl2  = vh2 + ELEMS;
    __nv_bfloat16* a1hi = vl2 + ELEMS;
    __nv_bfloat16* a1lo = a1hi + ELEMS;
    __nv_bfloat16* a2hi = a1lo + ELEMS;
    __nv_bfloat16* a2lo = a2hi + ELEMS;
    __nv_bfloat16* wbase = a2lo + ELEMS;

    dim3 wg((WEL/4 + 255)/256, 8);
    split_w_kernel<<<wg, 256>>>(wp, wbase);

    ln_split_kernel<<<ROWS, 256>>>(x1, ln1_g, ln1_b, m1hi, m1lo);
    ln_split_kernel<<<ROWS, 256>>>(x2, ln2_g, ln2_b, m2hi, m2lo);

    cudaFuncSetAttribute(gemm_qk, cudaFuncAttributeMaxDynamicSharedMemorySize,
                         GSMEM);
    cudaFuncSetAttribute(gemm3, cudaFuncAttributeMaxDynamicSharedMemorySize,
                         GSMEM);
    cudaFuncSetAttribute(attn_hmma, cudaFuncAttributeMaxDynamicSharedMemorySize,
                         ASMEM);

    dim3 gg(D_MODEL / 128, ROWS / 128);   // (6, 64)

    // Q,K projections: 4 jobs in one launch (measured faster in R13)
    {
        QKJobs jb;
        int widx[4] = {0, 1, 3, 4};
        __nv_bfloat16* outs[4] = {q1, k1, q2, k2};
        for (int j = 0; j < 4; j++) {
            int i = widx[j];
            jb.A[j]    = (i < 3) ? m1hi : m2hi;
            jb.W[j]    = wbase + (size_t)i * 2 * WEL;
            jb.bias[j] = b_in[i];
            jb.C[j]    = outs[j];
        }
        dim3 gq(D_MODEL / 128, ROWS / 128, 4);
        gemm_qk<<<gq, 128, GSMEM>>>(jb);
    }

    // V projections: job-pure 3-pass
    gemm3<<<gg, 128, GSMEM>>>(m1hi, m1lo,
                           wbase + 2ull*2*WEL, wbase + 2ull*2*WEL + WEL,
                           b_in[2], nullptr, vh1, vl1, 2);
    gemm3<<<gg, 128, GSMEM>>>(m2hi, m2lo,
                           wbase + 5ull*2*WEL, wbase + 5ull*2*WEL + WEL,
                           b_in[5], nullptr, vh2, vl2, 2);

    dim3 ag(SEQ / 128, BATCH * HEADS);    // (8, 96)
    attn_hmma<<<ag, 128, ASMEM>>>(q1, k2, vh2, vl2, a1hi, a1lo);
    attn_hmma<<<ag, 128, ASMEM>>>(q2, k1, vh1, vl1, a2hi, a2lo);

    gemm3<<<gg, 128, GSMEM>>>(a1hi, a1lo, wbase + 6ull*2*WEL, wbase + 6ull*2*WEL + WEL,
                           b_in[6], out, nullptr, nullptr, 0);
    gemm3<<<gg, 128, GSMEM>>>(a2hi, a2lo, wbase + 7ull*2*WEL, wbase + 7ull*2*WEL + WEL,
                           b_in[7], out + ELEMS, nullptr, nullptr, 0);
}

// round 16
// speedup vs baseline: 1.3384x; 1.0270x over previous
#include <cuda_runtime.h>
#include <cuda_bf16.h>
#include <stdint.h>
#include <math.h>

#define D_MODEL 768
#define HEADS   12
#define DH      64
#define SEQ     1024
#define BATCH   8
#define ROWS    (BATCH*SEQ)        /* 8192 */
#define ELEMS   (ROWS*D_MODEL)     /* 6291456 */
#define WEL     (D_MODEL*D_MODEL)  /* 589824 */

__device__ __nv_bfloat16 g_bf16[16ull * ELEMS + 16ull * WEL];

// ---------------------------------------------------------------------------
// PTX helpers
// ---------------------------------------------------------------------------
__device__ __forceinline__ uint32_t smem_u32(const void* p) {
    return (uint32_t)__cvta_generic_to_shared(p);
}
__device__ __forceinline__ void ldsm_x4(uint32_t r[4], uint32_t addr) {
    asm volatile("ldmatrix.sync.aligned.m8n8.x4.shared.b16 {%0,%1,%2,%3}, [%4];"
                 : "=r"(r[0]), "=r"(r[1]), "=r"(r[2]), "=r"(r[3]) : "r"(addr));
}
__device__ __forceinline__ void ldsm_x4_t(uint32_t r[4], uint32_t addr) {
    asm volatile("ldmatrix.sync.aligned.m8n8.x4.trans.shared.b16 {%0,%1,%2,%3}, [%4];"
                 : "=r"(r[0]), "=r"(r[1]), "=r"(r[2]), "=r"(r[3]) : "r"(addr));
}
__device__ __forceinline__ void mma_bf16(float d[4], const uint32_t a[4],
                                         const uint32_t b[2]) {
    asm volatile(
        "mma.sync.aligned.m16n8k16.row.col.f32.bf16.bf16.f32 "
        "{%0,%1,%2,%3}, {%4,%5,%6,%7}, {%8,%9}, {%0,%1,%2,%3};"
        : "+f"(d[0]), "+f"(d[1]), "+f"(d[2]), "+f"(d[3])
        : "r"(a[0]), "r"(a[1]), "r"(a[2]), "r"(a[3]), "r"(b[0]), "r"(b[1]));
}
__device__ __forceinline__ uint32_t pack_bf2(float a, float b) {
    __nv_bfloat162 t = __floats2bfloat162_rn(a, b);
    return *(uint32_t*)&t;
}
__device__ __forceinline__ void cp16(uint32_t s, const void* g) {
    asm volatile("cp.async.cg.shared.global [%0], [%1], 16;" :: "r"(s), "l"(g));
}
__device__ __forceinline__ void cp_commit() {
    asm volatile("cp.async.commit_group;" ::: "memory");
}
template<int N> __device__ __forceinline__ void cp_wait() {
    asm volatile("cp.async.wait_group %0;" :: "n"(N) : "memory");
}

// ---------------------------------------------------------------------------
// LayerNorm fused with hi/lo bf16 split. One block per row, 256 threads.
// ---------------------------------------------------------------------------
__global__ __launch_bounds__(256)
void ln_split_kernel(const float* __restrict__ x, const float* __restrict__ g,
                     const float* __restrict__ b,
                     __nv_bfloat16* __restrict__ ohi, __nv_bfloat16* __restrict__ olo)
{
    __shared__ float red[16];
    int row = blockIdx.x;
    int tid = threadIdx.x;
    const float* xp = x + (size_t)row * D_MODEL;
    float v0 = xp[tid], v1 = xp[tid + 256], v2 = xp[tid + 512];
    float s  = v0 + v1 + v2;
    float sq = v0*v0 + v1*v1 + v2*v2;
    #pragma unroll
    for (int o = 16; o > 0; o >>= 1) {
        s  += __shfl_down_sync(0xffffffffu, s,  o);
        sq += __shfl_down_sync(0xffffffffu, sq, o);
    }
    int w = tid >> 5, l = tid & 31;
    if (l == 0) { red[w] = s; red[w + 8] = sq; }
    __syncthreads();
    if (tid < 32) {
        float ss = (tid < 8) ? red[tid]     : 0.f;
        float qq = (tid < 8) ? red[tid + 8] : 0.f;
        #pragma unroll
        for (int o = 4; o > 0; o >>= 1) {
            ss += __shfl_down_sync(0xffffffffu, ss, o);
            qq += __shfl_down_sync(0xffffffffu, qq, o);
        }
        if (tid == 0) { red[0] = ss; red[1] = qq; }
    }
    __syncthreads();
    float mu   = red[0] * (1.0f / D_MODEL);
    float var  = red[1] * (1.0f / D_MODEL) - mu * mu;
    float rstd = rsqrtf(var + 1e-5f);
    size_t base = (size_t)row * D_MODEL;
    #pragma unroll
    for (int e = 0; e < 3; e++) {
        int idx = tid + e * 256;
        float v = (e == 0) ? v0 : (e == 1) ? v1 : v2;
        float y = (v - mu) * rstd * g[idx] + b[idx];
        __nv_bfloat16 h = __float2bfloat16(y);
        ohi[base + idx] = h;
        olo[base + idx] = __float2bfloat16(y - __bfloat162float(h));
    }
}

// ---------------------------------------------------------------------------
// Fused hi/lo split of all 8 weight matrices (non-transposed, [k][n]).
// ---------------------------------------------------------------------------
struct WPtrs { const float* w[8]; };

__global__ __launch_bounds__(256)
void split_w_kernel(WPtrs p, __nv_bfloat16* __restrict__ base)
{
    int which = blockIdx.y;
    const float* x = p.w[which];
    __nv_bfloat16* hi = base + (size_t)which * 2 * WEL;
    __nv_bfloat16* lo = hi + WEL;
    int i = blockIdx.x * blockDim.x + threadIdx.x;
    if (i >= WEL / 4) return;
    float4 v = ((const float4*)x)[i];
    float va[4] = {v.x, v.y, v.z, v.w};
    __nv_bfloat16 h[4], l[4];
    #pragma unroll
    for (int e = 0; e < 4; e++) {
        h[e] = __float2bfloat16(va[e]);
        l[e] = __float2bfloat16(va[e] - __bfloat162float(h[e]));
    }
    ((__nv_bfloat162*)hi)[i*2]   = __nv_bfloat162(h[0], h[1]);
    ((__nv_bfloat162*)hi)[i*2+1] = __nv_bfloat162(h[2], h[3]);
    ((__nv_bfloat162*)lo)[i*2]   = __nv_bfloat162(l[0], l[1]);
    ((__nv_bfloat162*)lo)[i*2+1] = __nv_bfloat162(l[2], l[3]);
}

// ---------------------------------------------------------------------------
// GEMM smem layout (shared by both GEMM kernels)
// ---------------------------------------------------------------------------
#define AS_TYPE  (128 * 40 * 2)        /* 10240 */
#define AS_STAGE (2 * AS_TYPE)         /* 20480 */
#define BS_TYPE  (32 * 136 * 2)        /* 8704  */
#define BS_STAGE (2 * BS_TYPE)         /* 17408 */
#define BS_BASE  (2 * AS_STAGE)        /* 40960 */
#define GSMEM    (BS_BASE + 2 * BS_STAGE)  /* 75776 */
#define NCHUNK   (D_MODEL / 32)        /* 24 */

template<int NPASS>
__device__ __forceinline__ void gemm_load_chunk(
    uint32_t smb, int st, int k0, int bm, int bn, int tid,
    const __nv_bfloat16* __restrict__ Ahi, const __nv_bfloat16* __restrict__ Alo,
    const __nv_bfloat16* __restrict__ Whi, const __nv_bfloat16* __restrict__ Wlo)
{
    int ar = tid >> 2;            // 0..31
    int ac = (tid & 3) * 8;       // 0,8,16,24
    int br = tid >> 4;            // 0..7
    int bc = (tid & 15) * 8;      // 0..120
    #pragma unroll
    for (int rr = 0; rr < 4; rr++) {
        int r = ar + rr * 32;
        uint32_t dst = smb + st * AS_STAGE + (r * 40 + ac) * 2;
        cp16(dst, &Ahi[(size_t)(bm + r) * D_MODEL + k0 + ac]);
        if (NPASS == 3)
            cp16(dst + AS_TYPE, &Alo[(size_t)(bm + r) * D_MODEL + k0 + ac]);
    }
    #pragma unroll
    for (int rr = 0; rr < 4; rr++) {
        int r = br + rr * 8;
        uint32_t dst = smb + BS_BASE + st * BS_STAGE + (r * 136 + bc) * 2;
        cp16(dst, &Whi[(size_t)(k0 + r) * D_MODEL + bn + bc]);
        if (NPASS == 3)
            cp16(dst + BS_TYPE, &Wlo[(size_t)(k0 + r) * D_MODEL + bn + bc]);
    }
    cp_commit();
}

// ---------------------------------------------------------------------------
// Batched 1-pass QK GEMM: 4 jobs via blockIdx.z (measured win R13/R15).
// ---------------------------------------------------------------------------
struct QKJobs {
    const __nv_bfloat16* A[4];
    const __nv_bfloat16* W[4];
    const float*         bias[4];
    __nv_bfloat16*       C[4];
};

__global__ __launch_bounds__(128, 2)
void gemm_qk(QKJobs jb)
{
    extern __shared__ char smg[];
    uint32_t smb = smem_u32(smg);

    int z = blockIdx.z;
    const __nv_bfloat16* __restrict__ A = jb.A[z];
    const __nv_bfloat16* __restrict__ W = jb.W[z];
    const float* __restrict__ bias = jb.bias[z];
    __nv_bfloat16* __restrict__ C = jb.C[z];

    int tid  = threadIdx.x;
    int warp = tid >> 5, lane = tid & 31;
    int wm = (warp >> 1) * 64;
    int wn = (warp & 1) * 64;
    int bm = blockIdx.y * 128, bn = blockIdx.x * 128;

    float acc[4][8][4] = {};

    gemm_load_chunk<1>(smb, 0, 0, bm, bn, tid, A, nullptr, W, nullptr);

    #pragma unroll 1
    for (int ch = 0; ch < NCHUNK; ch++) {
        int st = ch & 1;
        if (ch + 1 < NCHUNK) {
            gemm_load_chunk<1>(smb, (ch + 1) & 1, (ch + 1) * 32, bm, bn, tid,
                               A, nullptr, W, nullptr);
            cp_wait<1>();
        } else {
            cp_wait<0>();
        }
        __syncthreads();

        #pragma unroll
        for (int kk = 0; kk < 32; kk += 16) {
            uint32_t ah[4][4];
            uint32_t bh[8][2];
            #pragma unroll
            for (int mi = 0; mi < 4; mi++) {
                uint32_t aoff = ((wm + mi * 16 + (lane & 15)) * 40 +
                                 kk + (lane >> 4) * 8) * 2;
                ldsm_x4(ah[mi], smb + st * AS_STAGE + aoff);
            }
            #pragma unroll
            for (int nj2 = 0; nj2 < 4; nj2++) {
                uint32_t r4[4];
                uint32_t boff = ((kk + (lane & 15)) * 136 +
                                 wn + nj2 * 16 + (lane >> 4) * 8) * 2;
                ldsm_x4_t(r4, smb + BS_BASE + st * BS_STAGE + boff);
                bh[nj2*2+0][0] = r4[0]; bh[nj2*2+0][1] = r4[1];
                bh[nj2*2+1][0] = r4[2]; bh[nj2*2+1][1] = r4[3];
            }
            #pragma unroll
            for (int mi = 0; mi < 4; mi++)
                #pragma unroll
                for (int nj = 0; nj < 8; nj++)
                    mma_bf16(acc[mi][nj], ah[mi], bh[nj]);
        }
        __syncthreads();
    }

    #pragma unroll
    for (int mi = 0; mi < 4; mi++) {
        #pragma unroll
        for (int nj = 0; nj < 8; nj++) {
            int row0 = bm + wm + mi * 16 + (lane >> 2);
            int col  = bn + wn + nj * 8 + (lane & 3) * 2;
            float b0 = bias[col], b1 = bias[col + 1];
            #pragma unroll
            for (int half = 0; half < 2; half++) {
                int row = row0 + half * 8;
                float v0 = acc[mi][nj][half * 2 + 0] + b0;
                float v1 = acc[mi][nj][half * 2 + 1] + b1;
                int bb = row >> 10;
                int n  = row & (SEQ - 1);
                int h  = col >> 6;
                int dh = col & 63;
                size_t idx = (((size_t)(bb * HEADS + h)) * SEQ + n) * DH + dh;
                *(uint32_t*)&C[idx] = pack_bf2(v0, v1);
            }
        }
    }
}

// ---------------------------------------------------------------------------
// 3-pass split-bf16 GEMM, PAIRED: 2 jobs merged along grid.y.
// blockIdx.y in [0,128): job = y >> 6, bm = (y & 63) * 128.
// mode 0: fp32 row-major; mode 2: bf16 hi/lo head layout.
// ---------------------------------------------------------------------------
struct G3Jobs {
    const __nv_bfloat16* Ahi[2];
    const __nv_bfloat16* Alo[2];
    const __nv_bfloat16* Whi[2];
    const __nv_bfloat16* Wlo[2];
    const float*         bias[2];
    float*               Cf[2];
    __nv_bfloat16*       Ch[2];
    __nv_bfloat16*       Cl[2];
};

__global__ __launch_bounds__(128, 2)
void gemm3(G3Jobs jb, int mode)
{
    extern __shared__ char smg[];
    uint32_t smb = smem_u32(smg);

    int job = blockIdx.y >> 6;
    const __nv_bfloat16* __restrict__ Ahi = jb.Ahi[job];
    const __nv_bfloat16* __restrict__ Alo = jb.Alo[job];
    const __nv_bfloat16* __restrict__ Whi = jb.Whi[job];
    const __nv_bfloat16* __restrict__ Wlo = jb.Wlo[job];
    const float* __restrict__ bias = jb.bias[job];

    int tid  = threadIdx.x;
    int warp = tid >> 5, lane = tid & 31;
    int wm = (warp >> 1) * 64;
    int wn = (warp & 1) * 64;
    int bm = (blockIdx.y & 63) * 128, bn = blockIdx.x * 128;

    float acc[4][8][4] = {};

    gemm_load_chunk<3>(smb, 0, 0, bm, bn, tid, Ahi, Alo, Whi, Wlo);

    #pragma unroll 1
    for (int ch = 0; ch < NCHUNK; ch++) {
        int st = ch & 1;
        if (ch + 1 < NCHUNK) {
            gemm_load_chunk<3>(smb, (ch + 1) & 1, (ch + 1) * 32, bm, bn, tid,
                               Ahi, Alo, Whi, Wlo);
            cp_wait<1>();
        } else {
            cp_wait<0>();
        }
        __syncthreads();

        #pragma unroll
        for (int kk = 0; kk < 32; kk += 16) {
            uint32_t ah[4][4], al[4][4];
            uint32_t bh[8][2], bl[8][2];
            #pragma unroll
            for (int mi = 0; mi < 4; mi++) {
                uint32_t aoff = ((wm + mi * 16 + (lane & 15)) * 40 +
                                 kk + (lane >> 4) * 8) * 2;
                ldsm_x4(ah[mi], smb + st * AS_STAGE + aoff);
                ldsm_x4(al[mi], smb + st * AS_STAGE + AS_TYPE + aoff);
            }
            #pragma unroll
            for (int nj2 = 0; nj2 < 4; nj2++) {
                uint32_t r4[4];
                uint32_t boff = ((kk + (lane & 15)) * 136 +
                                 wn + nj2 * 16 + (lane >> 4) * 8) * 2;
                ldsm_x4_t(r4, smb + BS_BASE + st * BS_STAGE + boff);
                bh[nj2*2+0][0] = r4[0]; bh[nj2*2+0][1] = r4[1];
                bh[nj2*2+1][0] = r4[2]; bh[nj2*2+1][1] = r4[3];
                ldsm_x4_t(r4, smb + BS_BASE + st * BS_STAGE + BS_TYPE + boff);
                bl[nj2*2+0][0] = r4[0]; bl[nj2*2+0][1] = r4[1];
                bl[nj2*2+1][0] = r4[2]; bl[nj2*2+1][1] = r4[3];
            }
            #pragma unroll
            for (int mi = 0; mi < 4; mi++)
                #pragma unroll
                for (int nj = 0; nj < 8; nj++) {
                    mma_bf16(acc[mi][nj], ah[mi], bh[nj]);
                    mma_bf16(acc[mi][nj], ah[mi], bl[nj]);
                    mma_bf16(acc[mi][nj], al[mi], bh[nj]);
                }
        }
        __syncthreads();
    }

    float* __restrict__ Cf = jb.Cf[job];
    __nv_bfloat16* __restrict__ Ch = jb.Ch[job];
    __nv_bfloat16* __restrict__ Cl = jb.Cl[job];
    #pragma unroll
    for (int mi = 0; mi < 4; mi++) {
        #pragma unroll
        for (int nj = 0; nj < 8; nj++) {
            int row0 = bm + wm + mi * 16 + (lane >> 2);
            int col  = bn + wn + nj * 8 + (lane & 3) * 2;
            float b0 = bias[col], b1 = bias[col + 1];
            #pragma unroll
            for (int half = 0; half < 2; half++) {
                int row = row0 + half * 8;
                float v0 = acc[mi][nj][half * 2 + 0] + b0;
                float v1 = acc[mi][nj][half * 2 + 1] + b1;
                if (mode == 0) {
                    float2 v = make_float2(v0, v1);
                    *(float2*)&Cf[(size_t)row * D_MODEL + col] = v;
                } else {
                    int bb = row >> 10;
                    int n  = row & (SEQ - 1);
                    int h  = col >> 6;
                    int dh = col & 63;
                    size_t idx = (((size_t)(bb * HEADS + h)) * SEQ + n) * DH + dh;
                    float h0 = __bfloat162float(__float2bfloat16(v0));
                    float h1 = __bfloat162float(__float2bfloat16(v1));
                    *(uint32_t*)&Ch[idx] = pack_bf2(h0, h1);
                    *(uint32_t*)&Cl[idx] = pack_bf2(v0 - h0, v1 - h1);
                }
            }
        }
    }
}

// ---------------------------------------------------------------------------
// HMMA flash attention, 128 threads, 4 warps of m32.
// K/Vh/Vl staged via 3-stage cp.async pipeline in dynamic smem.
// ---------------------------------------------------------------------------
#define APAD 72
#define AQ_BYTES  (128 * APAD * 2)     /* 18432 */
#define AKV_BYTES (64 * APAD * 2)      /* 9216  */
#define ASTAGE    (3 * AKV_BYTES)      /* 27648 */
#define NSTAGES   3
#define ASMEM     (AQ_BYTES + NSTAGES * ASTAGE)  /* 101376 */

__device__ __forceinline__ void attn_load_kv(
    uint32_t smb, int st, int kv0, int tid,
    const __nv_bfloat16* __restrict__ Kp,
    const __nv_bfloat16* __restrict__ Vhq,
    const __nv_bfloat16* __restrict__ Vlq)
{
    uint32_t base = smb + AQ_BYTES + st * ASTAGE;
    #pragma unroll
    for (int j = 0; j < 4; j++) {
        int i = tid + j * 128;            // 0..511
        int r = i >> 3, c = (i & 7) * 8;
        size_t gi = (size_t)(kv0 + r) * DH + c;
        uint32_t off = (r * APAD + c) * 2;
        cp16(base + off,                 &Kp[gi]);
        cp16(base + AKV_BYTES + off,     &Vhq[gi]);
        cp16(base + 2 * AKV_BYTES + off, &Vlq[gi]);
    }
    cp_commit();
}

__global__ __launch_bounds__(128, 2)
void attn_hmma(const __nv_bfloat16* __restrict__ Q, const __nv_bfloat16* __restrict__ K,
               const __nv_bfloat16* __restrict__ Vhp, const __nv_bfloat16* __restrict__ Vlp,
               __nv_bfloat16* __restrict__ Ohi, __nv_bfloat16* __restrict__ Olo)
{
    extern __shared__ char sma[];
    uint32_t smb = smem_u32(sma);
    __nv_bfloat16* Qs = (__nv_bfloat16*)sma;   // [128][APAD]

    int tid = threadIdx.x, warp = tid >> 5, lane = tid & 31;
    int bh = blockIdx.y;
    int q0 = blockIdx.x * 128;
    const __nv_bfloat16* Qp  = Q   + (size_t)bh * SEQ * DH + (size_t)q0 * DH;
    const __nv_bfloat16* Kp  = K   + (size_t)bh * SEQ * DH;
    const __nv_bfloat16* Vhq = Vhp + (size_t)bh * SEQ * DH;
    const __nv_bfloat16* Vlq = Vlp + (size_t)bh * SEQ * DH;

    #pragma unroll
    for (int i = tid; i < 128 * 64 / 8; i += 128) {
        int r = i >> 3, c = (i & 7) * 8;
        *(uint4*)&Qs[r * APAD + c] = *(const uint4*)&Qp[(size_t)r * DH + c];
    }

    // prologue: prefetch chunks 0 and 1
    attn_load_kv(smb, 0, 0, tid, Kp, Vhq, Vlq);
    attn_load_kv(smb, 1, 64, tid, Kp, Vhq, Vlq);

    int wm = warp * 32;
    float mst[2][2], lst[2][2];
    #pragma unroll
    for (int mi = 0; mi < 2; mi++) {
        mst[mi][0] = -INFINITY; mst[mi][1] = -INFINITY;
        lst[mi][0] = 0.f;       lst[mi][1] = 0.f;
    }
    float o[2][8][4] = {};

    #pragma unroll 1
    for (int kv0 = 0; kv0 < SEQ; kv0 += 64) {
        int ch = kv0 >> 6;
        int st = ch % NSTAGES;
        uint32_t kb = smb + AQ_BYTES + st * ASTAGE;
        uint32_t vhb = kb + AKV_BYTES;
        uint32_t vlb = kb + 2 * AKV_BYTES;

        if (kv0 + 128 < SEQ) {
            attn_load_kv(smb, (ch + 2) % NSTAGES, kv0 + 128, tid, Kp, Vhq, Vlq);
            cp_wait<2>();
        } else if (kv0 + 64 < SEQ) {
            cp_wait<1>();
        } else {
            cp_wait<0>();
        }
        __syncthreads();

        float s[2][8][4] = {};
        #pragma unroll
        for (int d = 0; d < 64; d += 16) {
            uint32_t a0[4], a1[4];
            int acol = d + (lane >> 4) * 8;
            ldsm_x4(a0, smb + ((wm +      (lane & 15)) * APAD + acol) * 2);
            ldsm_x4(a1, smb + ((wm + 16 + (lane & 15)) * APAD + acol) * 2);
            #pragma unroll
            for (int g = 0; g < 4; g++) {
                uint32_t r4[4];
                ldsm_x4(r4, kb + ((g * 16 + (lane & 15)) * APAD + acol) * 2);
                uint32_t b0[2] = {r4[0], r4[2]};
                uint32_t b1[2] = {r4[1], r4[3]};
                mma_bf16(s[0][2 * g],     a0, b0);
                mma_bf16(s[0][2 * g + 1], a0, b1);
                mma_bf16(s[1][2 * g],     a1, b0);
                mma_bf16(s[1][2 * g + 1], a1, b1);
            }
        }

        uint32_t phh[2][4][4], pll[2][4][4];
        #pragma unroll
        for (int mi = 0; mi < 2; mi++) {
            float tm0 = -INFINITY, tm1 = -INFINITY;
            #pragma unroll
            for (int f = 0; f < 8; f++) {
                #pragma unroll
                for (int j = 0; j < 4; j++) s[mi][f][j] *= 0.125f;
                tm0 = fmaxf(tm0, fmaxf(s[mi][f][0], s[mi][f][1]));
                tm1 = fmaxf(tm1, fmaxf(s[mi][f][2], s[mi][f][3]));
            }
            tm0 = fmaxf(tm0, __shfl_xor_sync(0xffffffffu, tm0, 1));
            tm0 = fmaxf(tm0, __shfl_xor_sync(0xffffffffu, tm0, 2));
            tm1 = fmaxf(tm1, __shfl_xor_sync(0xffffffffu, tm1, 1));
            tm1 = fmaxf(tm1, __shfl_xor_sync(0xffffffffu, tm1, 2));
            float mn0 = fmaxf(mst[mi][0], tm0), mn1 = fmaxf(mst[mi][1], tm1);
            float al0 = __expf(mst[mi][0] - mn0), al1 = __expf(mst[mi][1] - mn1);
            mst[mi][0] = mn0; mst[mi][1] = mn1;

            float rs0 = 0.f, rs1 = 0.f;
            #pragma unroll
            for (int f = 0; f < 8; f++) {
                s[mi][f][0] = __expf(s[mi][f][0] - mn0);
                s[mi][f][1] = __expf(s[mi][f][1] - mn0);
                s[mi][f][2] = __expf(s[mi][f][2] - mn1);
                s[mi][f][3] = __expf(s[mi][f][3] - mn1);
                rs0 += s[mi][f][0] + s[mi][f][1];
                rs1 += s[mi][f][2] + s[mi][f][3];
            }
            rs0 += __shfl_xor_sync(0xffffffffu, rs0, 1);
            rs0 += __shfl_xor_sync(0xffffffffu, rs0, 2);
            rs1 += __shfl_xor_sync(0xffffffffu, rs1, 1);
            rs1 += __shfl_xor_sync(0xffffffffu, rs1, 2);
            lst[mi][0] = lst[mi][0] * al0 + rs0;
            lst[mi][1] = lst[mi][1] * al1 + rs1;

            #pragma unroll
            for (int f = 0; f < 8; f++) {
                o[mi][f][0] *= al0; o[mi][f][1] *= al0;
                o[mi][f][2] *= al1; o[mi][f][3] *= al1;
            }

            #pragma unroll
            for (int c = 0; c < 4; c++) {
                float* f0 = s[mi][2 * c];
                float* f1 = s[mi][2 * c + 1];
                float v8[8] = {f0[0], f0[1], f0[2], f0[3],
                               f1[0], f1[1], f1[2], f1[3]};
                float hi8[8];
                #pragma unroll
                for (int e = 0; e < 8; e++)
                    hi8[e] = __bfloat162float(__float2bfloat16(v8[e]));
                phh[mi][c][0] = pack_bf2(hi8[0], hi8[1]);
                phh[mi][c][1] = pack_bf2(hi8[2], hi8[3]);
                phh[mi][c][2] = pack_bf2(hi8[4], hi8[5]);
                phh[mi][c][3] = pack_bf2(hi8[6], hi8[7]);
                pll[mi][c][0] = pack_bf2(v8[0] - hi8[0], v8[1] - hi8[1]);
                pll[mi][c][1] = pack_bf2(v8[2] - hi8[2], v8[3] - hi8[3]);
                pll[mi][c][2] = pack_bf2(v8[4] - hi8[4], v8[5] - hi8[5]);
                pll[mi][c][3] = pack_bf2(v8[6] - hi8[6], v8[7] - hi8[7]);
            }
        }

        #pragma unroll
        for (int c = 0; c < 4; c++) {
            #pragma unroll
            for (int g = 0; g < 4; g++) {
                uint32_t r4[4];
                uint32_t voff = ((c * 16 + (lane & 15)) * APAD +
                                 g * 16 + (lane >> 4) * 8) * 2;
                ldsm_x4_t(r4, vhb + voff);
                uint32_t b0[2] = {r4[0], r4[1]};
                uint32_t b1[2] = {r4[2], r4[3]};
                #pragma unroll
                for (int mi = 0; mi < 2; mi++) {
                    mma_bf16(o[mi][2 * g],     phh[mi][c], b0);
                    mma_bf16(o[mi][2 * g + 1], phh[mi][c], b1);
                    mma_bf16(o[mi][2 * g],     pll[mi][c], b0);
                    mma_bf16(o[mi][2 * g + 1], pll[mi][c], b1);
                }
                ldsm_x4_t(r4, vlb + voff);
                uint32_t c0[2] = {r4[0], r4[1]};
                uint32_t c1[2] = {r4[2], r4[3]};
                #pragma unroll
                for (int mi = 0; mi < 2; mi++) {
                    mma_bf16(o[mi][2 * g],     phh[mi][c], c0);
                    mma_bf16(o[mi][2 * g + 1], phh[mi][c], c1);
                }
            }
        }
        __syncthreads();
    }

    int b = bh / HEADS, h = bh % HEADS;
    #pragma unroll
    for (int mi = 0; mi < 2; mi++) {
        float inv0 = 1.f / lst[mi][0], inv1 = 1.f / lst[mi][1];
        int r0 = q0 + wm + mi * 16 + (lane >> 2);
        #pragma unroll
        for (int g = 0; g < 8; g++) {
            int col = h * DH + g * 8 + (lane & 3) * 2;
            #pragma unroll
            for (int half = 0; half < 2; half++) {
                int n = r0 + half * 8;
                float inv = half ? inv1 : inv0;
                float v0 = o[mi][g][half * 2 + 0] * inv;
                float v1 = o[mi][g][half * 2 + 1] * inv;
                float h0 = __bfloat162float(__float2bfloat16(v0));
                float h1 = __bfloat162float(__float2bfloat16(v1));
                size_t idx = ((size_t)(b * SEQ + n)) * D_MODEL + col;
                *(uint32_t*)&Ohi[idx] = pack_bf2(h0, h1);
                *(uint32_t*)&Olo[idx] = pack_bf2(v0 - h0, v1 - h1);
            }
        }
    }
}

// ---------------------------------------------------------------------------
extern "C" void kernel_launch(void* const* d_in, const int* in_sizes, int n_in,
                              void* d_out, int out_size)
{
    const float* x1    = (const float*)d_in[0];
    const float* x2    = (const float*)d_in[1];
    const float* ln1_g = (const float*)d_in[2];
    const float* ln1_b = (const float*)d_in[3];
    const float* ln2_g = (const float*)d_in[4];
    const float* ln2_b = (const float*)d_in[5];
    WPtrs wp;
    wp.w[0] = (const float*)d_in[6];
    wp.w[1] = (const float*)d_in[8];
    wp.w[2] = (const float*)d_in[10];
    wp.w[3] = (const float*)d_in[12];
    wp.w[4] = (const float*)d_in[14];
    wp.w[5] = (const float*)d_in[16];
    wp.w[6] = (const float*)d_in[18];
    wp.w[7] = (const float*)d_in[20];
    const float* b_in[8] = {
        (const float*)d_in[7],  (const float*)d_in[9],  (const float*)d_in[11],
        (const float*)d_in[13], (const float*)d_in[15], (const float*)d_in[17],
        (const float*)d_in[19], (const float*)d_in[21]
    };
    float* out = (float*)d_out;

    __nv_bfloat16* bf;
    cudaGetSymbolAddress((void**)&bf, g_bf16);

    __nv_bfloat16* m1hi = bf;
    __nv_bfloat16* m1lo = m1hi + ELEMS;
    __nv_bfloat16* m2hi = m1lo + ELEMS;
    __nv_bfloat16* m2lo = m2hi + ELEMS;
    __nv_bfloat16* q1   = m2lo + ELEMS;
    __nv_bfloat16* k1   = q1 + ELEMS;
    __nv_bfloat16* vh1  = k1 + ELEMS;
    __nv_bfloat16* vl1  = vh1 + ELEMS;
    __nv_bfloat16* q2   = vl1 + ELEMS;
    __nv_bfloat16* k2   = q2 + ELEMS;
    __nv_bfloat16* vh2  = k2 + ELEMS;
    __nv_bfloat16* vl2  = vh2 + ELEMS;
    __nv_bfloat16* a1hi = vl2 + ELEMS;
    __nv_bfloat16* a1lo = a1hi + ELEMS;
    __nv_bfloat16* a2hi = a1lo + ELEMS;
    __nv_bfloat16* a2lo = a2hi + ELEMS;
    __nv_bfloat16* wbase = a2lo + ELEMS;

    dim3 wg((WEL/4 + 255)/256, 8);
    split_w_kernel<<<wg, 256>>>(wp, wbase);

    ln_split_kernel<<<ROWS, 256>>>(x1, ln1_g, ln1_b, m1hi, m1lo);
    ln_split_kernel<<<ROWS, 256>>>(x2, ln2_g, ln2_b, m2hi, m2lo);

    cudaFuncSetAttribute(gemm_qk, cudaFuncAttributeMaxDynamicSharedMemorySize,
                         GSMEM);
    cudaFuncSetAttribute(gemm3, cudaFuncAttributeMaxDynamicSharedMemorySize,
                         GSMEM);
    cudaFuncSetAttribute(attn_hmma, cudaFuncAttributeMaxDynamicSharedMemorySize,
                         ASMEM);

    // Q,K projections: 4 jobs in one launch
    {
        QKJobs jb;
        int widx[4] = {0, 1, 3, 4};
        __nv_bfloat16* outs[4] = {q1, k1, q2, k2};
        for (int j = 0; j < 4; j++) {
            int i = widx[j];
            jb.A[j]    = (i < 3) ? m1hi : m2hi;
            jb.W[j]    = wbase + (size_t)i * 2 * WEL;
            jb.bias[j] = b_in[i];
            jb.C[j]    = outs[j];
        }
        dim3 gq(D_MODEL / 128, ROWS / 128, 4);
        gemm_qk<<<gq, 128, GSMEM>>>(jb);
    }

    // V projections: pair merged along grid.y
    {
        G3Jobs jb = {};
        jb.Ahi[0] = m1hi; jb.Alo[0] = m1lo;
        jb.Whi[0] = wbase + 2ull * 2 * WEL; jb.Wlo[0] = wbase + 2ull * 2 * WEL + WEL;
        jb.bias[0] = b_in[2]; jb.Ch[0] = vh1; jb.Cl[0] = vl1;
        jb.Ahi[1] = m2hi; jb.Alo[1] = m2lo;
        jb.Whi[1] = wbase + 5ull * 2 * WEL; jb.Wlo[1] = wbase + 5ull * 2 * WEL + WEL;
        jb.bias[1] = b_in[5]; jb.Ch[1] = vh2; jb.Cl[1] = vl2;
        dim3 gv(D_MODEL / 128, 2 * (ROWS / 128));   // (6, 128)
        gemm3<<<gv, 128, GSMEM>>>(jb, 2);
    }

    dim3 ag(SEQ / 128, BATCH * HEADS);    // (8, 96) — job-pure
    attn_hmma<<<ag, 128, ASMEM>>>(q1, k2, vh2, vl2, a1hi, a1lo);
    attn_hmma<<<ag, 128, ASMEM>>>(q2, k1, vh1, vl1, a2hi, a2lo);

    // Output projections: pair merged along grid.y
    {
        G3Jobs jb = {};
        jb.Ahi[0] = a1hi; jb.Alo[0] = a1lo;
        jb.Whi[0] = wbase + 6ull * 2 * WEL; jb.Wlo[0] = wbase + 6ull * 2 * WEL + WEL;
        jb.bias[0] = b_in[6]; jb.Cf[0] = out;
        jb.Ahi[1] = a2hi; jb.Alo[1] = a2lo;
        jb.Whi[1] = wbase + 7ull * 2 * WEL; jb.Wlo[1] = wbase + 7ull * 2 * WEL + WEL;
        jb.bias[1] = b_in[7]; jb.Cf[1] = out + ELEMS;
        dim3 go(D_MODEL / 128, 2 * (ROWS / 128));   // (6, 128)
        gemm3<<<go, 128, GSMEM>>>(jb, 0);
    }
}